// round 4
// baseline (speedup 1.0000x reference)
#include <cuda_runtime.h>

#define B_N 8
#define T_N 4096
#define CH  256
#define NL  8
#define TT  128
#define KC  32
#define BSW 384   // extended Bs row width for the dilated-conv kernel

typedef unsigned long long u64;

// ---- f32x2 packed helpers ----
__device__ __forceinline__ u64 bcast2(float v) {
    u64 r; unsigned int b = __float_as_uint(v);
    asm("mov.b64 %0, {%1, %1};" : "=l"(r) : "r"(b));
    return r;
}
__device__ __forceinline__ void ffma2(u64& acc, u64 a, u64 b) {
    asm("fma.rn.f32x2 %0, %1, %2, %0;" : "+l"(acc) : "l"(a), "l"(b));
}
__device__ __forceinline__ float2 unpack2(u64 v) {
    float2 f;
    asm("mov.b64 {%0, %1}, %2;" : "=f"(f.x), "=f"(f.y) : "l"(v));
    return f;
}

// ---- scratch (device globals; no allocations allowed) ----
__device__ float g_x[B_N * CH * T_N];        // 32 MB
__device__ float g_acts[B_N * CH * T_N];     // 32 MB
__device__ float g_outacc[B_N * CH * T_N];   // 32 MB
__device__ float g_inw_t[NL * 3 * CH * 512]; // [layer][k][c][o]  (o contiguous)
__device__ float g_rsw_t[NL * CH * 512];     // [layer][c][o]
__device__ float g_condw_t[NL * 80 * 512];   // [layer][m][o]

// ---------------- weight transposes (coalesced-dst layouts) ----------------
__global__ void tr_inw_kernel(const float* __restrict__ w) {
    int idx = blockIdx.x * 256 + threadIdx.x;
    if (idx >= NL * 512 * CH * 3) return;
    int k = idx % 3;
    int c = (idx / 3) % CH;
    int o = (idx / (3 * CH)) % 512;
    int i = idx / (3 * CH * 512);
    g_inw_t[((i * 3 + k) * CH + c) * 512 + o] = w[idx];
}

__global__ void tr_rsw_kernel(const float* __restrict__ w) {
    int idx = blockIdx.x * 256 + threadIdx.x;
    if (idx >= NL * 512 * CH) return;
    int c = idx & (CH - 1);
    int o = (idx >> 8) & 511;
    int i = idx >> 17;
    g_rsw_t[(i * CH + c) * 512 + o] = w[idx];
}

__global__ void tr_cw_kernel(const float* __restrict__ w) {
    int idx = blockIdx.x * 256 + threadIdx.x;
    if (idx >= NL * 512 * 80) return;
    int m = idx % 80;
    int og = idx / 80;           // global out channel 0..4095
    int i = og >> 9;
    int o = og & 511;
    g_condw_t[(i * 80 + m) * 512 + o] = w[idx];
}

// ---------------- start conv (1x1, 4->256) + zero out_acc ----------------
__global__ void start_kernel(const float* __restrict__ f,
                             const float* __restrict__ sw,
                             const float* __restrict__ sb) {
    int idx = blockIdx.x * 256 + threadIdx.x;   // over B*CH*T
    int t = idx & (T_N - 1);
    int c = (idx >> 12) & (CH - 1);
    int b = idx >> 20;
    const float* fb = f + (size_t)b * 8 * T_N;  // f0 = first 4 channels
    float acc = sb[c];
#pragma unroll
    for (int i = 0; i < 4; i++)
        acc = fmaf(fb[(size_t)i * T_N + t], sw[c * 4 + i], acc);
    g_x[idx] = acc;
    g_outacc[idx] = 0.f;
}

// ---------------- main dilated conv + cond conv + gate ----------------
// Block: (t-tile 128) x (64 j-pairs = 128 out rows) for one batch.
// Accumulators are f32x2 pairs along the output-row dimension:
//   acc2[0..1][u] = rows j0+ty*4+{0,1},{2,3}         (tanh half)
//   acc2[2..3][u] = rows 256+j0+ty*4+{0,1},{2,3}     (sigmoid half)
// cols t0 + tx + 16u, u<8.
extern __shared__ float smem_dyn[];
__global__ __launch_bounds__(256) void layer_conv_kernel(
    const float* __restrict__ context,
    const float* __restrict__ in_b,
    const float* __restrict__ cond_b,
    int li, int d) {
    float* As = smem_dyn;                 // [3][KC][128]
    float* Bs = smem_dyn + 3 * KC * 128;  // [KC][BSW]

    int tid = threadIdx.x;
    int tx = tid & 15;
    int ty = tid >> 4;
    int t0 = blockIdx.x * TT;
    int j0 = blockIdx.y * 64;
    int b  = blockIdx.z;

    const float* xb = g_x + (size_t)b * CH * T_N;
    const float* wt = g_inw_t + (size_t)li * 3 * CH * 512;

    u64 acc2[4][8];
#pragma unroll
    for (int i = 0; i < 4; i++)
#pragma unroll
        for (int u = 0; u < 8; u++) acc2[i][u] = 0ULL;

    // ===== x part: 3 dilated taps share one extended window per c-chunk =====
    for (int c0 = 0; c0 < CH; c0 += KC) {
        // As: 3*KC*128 floats -> 3072 float4, 12 per thread
#pragma unroll
        for (int e = 0; e < 12; e++) {
            int v = e * 256 + tid;
            int r4 = v & 31;
            int kkk = v >> 5;           // k*KC + kk
            int r = r4 * 4;
            int o = (r < 64) ? (j0 + r) : (256 + j0 + r - 64);
            int kk = kkk & (KC - 1);
            int k = kkk >> 5;
            float4 val = *(const float4*)(wt + ((size_t)(k * CH) + c0 + kk) * 512 + o);
            *(float4*)(As + kkk * 128 + r) = val;
        }
        // Bs: KC rows x 384 cols, window [t0-128, t0+256)
#pragma unroll
        for (int e = 0; e < 12; e++) {
            int v = e * 256 + tid;
            int c4 = v % 96;
            int kk = v / 96;
            int t = t0 - 128 + c4 * 4;
            float4 val = make_float4(0.f, 0.f, 0.f, 0.f);
            if (t >= 0 && t < T_N)
                val = *(const float4*)(xb + (size_t)(c0 + kk) * T_N + t);
            *(float4*)(Bs + kk * BSW + c4 * 4) = val;
        }
        __syncthreads();
#pragma unroll 4
        for (int kk = 0; kk < KC; kk++) {
#pragma unroll
            for (int k = 0; k < 3; k++) {
                const float* ap = As + (k * KC + kk) * 128;
                ulonglong2 A0 = *(const ulonglong2*)(ap + ty * 4);
                ulonglong2 A1 = *(const ulonglong2*)(ap + 64 + ty * 4);
                const float* bp = Bs + kk * BSW + 128 + (k - 1) * d + tx;
#pragma unroll
                for (int u = 0; u < 8; u++) {
                    u64 bv2 = bcast2(bp[u * 16]);
                    ffma2(acc2[0][u], A0.x, bv2);
                    ffma2(acc2[1][u], A0.y, bv2);
                    ffma2(acc2[2][u], A1.x, bv2);
                    ffma2(acc2[3][u], A1.y, bv2);
                }
            }
        }
        __syncthreads();
    }

    // ===== context part (1x1, K=80, zero-padded to KC chunks) =====
    const float* cwt = g_condw_t + (size_t)li * 80 * 512;
    const float* ctxb = context + (size_t)b * 80 * T_N;
    for (int m0 = 0; m0 < 80; m0 += KC) {
#pragma unroll
        for (int e = 0; e < 4; e++) {
            int v = e * 256 + tid;
            int r4 = v & 31;
            int kk = v >> 5;
            int r = r4 * 4;
            int o = (r < 64) ? (j0 + r) : (256 + j0 + r - 64);
            float4 val = make_float4(0.f, 0.f, 0.f, 0.f);
            if (m0 + kk < 80)
                val = *(const float4*)(cwt + (size_t)(m0 + kk) * 512 + o);
            *(float4*)(As + kk * 128 + r) = val;
        }
#pragma unroll
        for (int e = 0; e < 4; e++) {
            int v = e * 256 + tid;
            int c4 = v & 31;
            int kk = v >> 5;
            float4 val = make_float4(0.f, 0.f, 0.f, 0.f);
            if (m0 + kk < 80)
                val = *(const float4*)(ctxb + (size_t)(m0 + kk) * T_N + t0 + c4 * 4);
            *(float4*)(Bs + kk * BSW + 128 + c4 * 4) = val;
        }
        __syncthreads();
#pragma unroll 4
        for (int kk = 0; kk < KC; kk++) {
            const float* ap = As + kk * 128;
            ulonglong2 A0 = *(const ulonglong2*)(ap + ty * 4);
            ulonglong2 A1 = *(const ulonglong2*)(ap + 64 + ty * 4);
            const float* bp = Bs + kk * BSW + 128 + tx;
#pragma unroll
            for (int u = 0; u < 8; u++) {
                u64 bv2 = bcast2(bp[u * 16]);
                ffma2(acc2[0][u], A0.x, bv2);
                ffma2(acc2[1][u], A0.y, bv2);
                ffma2(acc2[2][u], A1.x, bv2);
                ffma2(acc2[3][u], A1.y, bv2);
            }
        }
        __syncthreads();
    }

    // ===== epilogue: biases + tanh*sigmoid gate =====
    const float* ibl = in_b + li * 512;
    const float* cbl = cond_b + li * 512;
    float* actsb = g_acts + (size_t)b * CH * T_N;
#pragma unroll
    for (int i2 = 0; i2 < 2; i2++) {
        int jj = j0 + ty * 4 + 2 * i2;     // row pair jj, jj+1
        float b1a = ibl[jj]       + cbl[jj];
        float b1b = ibl[jj + 1]   + cbl[jj + 1];
        float b2a = ibl[256 + jj]     + cbl[256 + jj];
        float b2b = ibl[256 + jj + 1] + cbl[256 + jj + 1];
        float* dst0 = actsb + (size_t)jj * T_N + t0 + tx;
        float* dst1 = dst0 + T_N;
#pragma unroll
        for (int u = 0; u < 8; u++) {
            float2 a1 = unpack2(acc2[i2][u]);
            float2 a2 = unpack2(acc2[2 + i2][u]);
            float s0 = 1.f / (1.f + __expf(-(a2.x + b2a)));
            float s1 = 1.f / (1.f + __expf(-(a2.y + b2b)));
            dst0[u * 16] = tanhf(a1.x + b1a) * s0;
            dst1[u * 16] = tanhf(a1.y + b1b) * s1;
        }
    }
}

// ---------------- res/skip 1x1 conv (256->512) + residual update ----------------
__global__ __launch_bounds__(256) void rs_kernel(const float* __restrict__ rs_b,
                                                 int li, int last) {
    __shared__ float As[KC * 128];
    __shared__ float Bs[KC * 128];

    int tid = threadIdx.x;
    int tx = tid & 15;
    int ty = tid >> 4;
    int t0 = blockIdx.x * TT;
    int j0 = blockIdx.y * 64;
    int b  = blockIdx.z;

    const float* wt = g_rsw_t + (size_t)li * CH * 512;
    const float* actsb = g_acts + (size_t)b * CH * T_N;

    u64 acc2[4][8];
#pragma unroll
    for (int i = 0; i < 4; i++)
#pragma unroll
        for (int u = 0; u < 8; u++) acc2[i][u] = 0ULL;

    for (int c0 = 0; c0 < CH; c0 += KC) {
#pragma unroll
        for (int e = 0; e < 4; e++) {
            int v = e * 256 + tid;
            int r4 = v & 31;
            int kk = v >> 5;
            int r = r4 * 4;
            int o = (r < 64) ? (j0 + r) : (256 + j0 + r - 64);
            *(float4*)(As + kk * 128 + r) =
                *(const float4*)(wt + (size_t)(c0 + kk) * 512 + o);
        }
#pragma unroll
        for (int e = 0; e < 4; e++) {
            int v = e * 256 + tid;
            int c4 = v & 31;
            int kk = v >> 5;
            *(float4*)(Bs + kk * 128 + c4 * 4) =
                *(const float4*)(actsb + (size_t)(c0 + kk) * T_N + t0 + c4 * 4);
        }
        __syncthreads();
#pragma unroll 4
        for (int kk = 0; kk < KC; kk++) {
            const float* ap = As + kk * 128;
            ulonglong2 A0 = *(const ulonglong2*)(ap + ty * 4);
            ulonglong2 A1 = *(const ulonglong2*)(ap + 64 + ty * 4);
            const float* bp = Bs + kk * 128 + tx;
#pragma unroll
            for (int u = 0; u < 8; u++) {
                u64 bv2 = bcast2(bp[u * 16]);
                ffma2(acc2[0][u], A0.x, bv2);
                ffma2(acc2[1][u], A0.y, bv2);
                ffma2(acc2[2][u], A1.x, bv2);
                ffma2(acc2[3][u], A1.y, bv2);
            }
        }
        __syncthreads();
    }

    const float* rbl = rs_b + li * 512;
    size_t base = (size_t)b * CH * T_N;
#pragma unroll
    for (int i2 = 0; i2 < 2; i2++) {
        int jj = j0 + ty * 4 + 2 * i2;     // row pair jj, jj+1
        float rb1a = rbl[jj];
        float rb1b = rbl[jj + 1];
        float rb2a = rbl[256 + jj];
        float rb2b = rbl[256 + jj + 1];
        size_t idx0 = base + (size_t)jj * T_N + t0 + tx;
        size_t idx1 = idx0 + T_N;
#pragma unroll
        for (int u = 0; u < 8; u++) {
            float2 r1 = unpack2(acc2[i2][u]);
            float2 r2 = unpack2(acc2[2 + i2][u]);
            size_t o = (size_t)u * 16;
            if (!last) {
                g_x[idx0 + o] += r1.x + rb1a;
                g_x[idx1 + o] += r1.y + rb1b;
                g_outacc[idx0 + o] += r2.x + rb2a;
                g_outacc[idx1 + o] += r2.y + rb2b;
            } else {
                g_outacc[idx0 + o] += r1.x + rb1a;   // last layer: output += rs[:256]
                g_outacc[idx1 + o] += r1.y + rb1b;
            }
        }
    }
}

// ---------------- end conv (1x1, 256->8) + affine transform ----------------
__global__ void end_kernel(const float* __restrict__ forecast,
                           const float* __restrict__ ew,
                           const float* __restrict__ eb,
                           float* __restrict__ out) {
    __shared__ float w[8 * CH];
    int tid = threadIdx.x;
    for (int e = tid; e < 8 * CH; e += 256) w[e] = ew[e];
    __syncthreads();

    int idx = blockIdx.x * 256 + tid;  // over B*T
    int t = idx & (T_N - 1);
    int b = idx >> 12;

    float acc[8];
#pragma unroll
    for (int o = 0; o < 8; o++) acc[o] = eb[o];
    const float* oa = g_outacc + (size_t)b * CH * T_N + t;
    for (int c = 0; c < CH; c++) {
        float v = oa[(size_t)c * T_N];
#pragma unroll
        for (int o = 0; o < 8; o++)
            acc[o] = fmaf(v, w[o * CH + c], acc[o]);
    }

    const float* fb = forecast + (size_t)b * 8 * T_N + t;
    float* cc = out + (size_t)b * 8 * T_N + t;                       // concat [B,8,T]
    float* lo = out + (size_t)B_N * 8 * T_N + (size_t)b * 4 * T_N + t; // log_s [B,4,T]
#pragma unroll
    for (int l = 0; l < 4; l++) {
        cc[(size_t)l * T_N] = fb[(size_t)l * T_N];                   // f0 passthrough
        float ls = acc[4 + l];                                       // log_s channel
        cc[(size_t)(4 + l) * T_N] =
            expf(ls) * fb[(size_t)(4 + l) * T_N] + acc[l];           // exp(ls)*f1 + b
        lo[(size_t)l * T_N] = ls;
    }
}

// ---------------- launch ----------------
static const int DIL[NL] = {1, 2, 4, 8, 16, 32, 64, 128};

extern "C" void kernel_launch(void* const* d_in, const int* in_sizes, int n_in,
                              void* d_out, int out_size) {
    const float* forecast = (const float*)d_in[0];
    const float* context  = (const float*)d_in[1];
    const float* start_w  = (const float*)d_in[2];
    const float* start_b  = (const float*)d_in[3];
    const float* cond_w   = (const float*)d_in[4];
    const float* cond_b   = (const float*)d_in[5];
    const float* in_w     = (const float*)d_in[6];
    const float* in_b     = (const float*)d_in[7];
    const float* rs_w     = (const float*)d_in[8];
    const float* rs_b     = (const float*)d_in[9];
    const float* end_w    = (const float*)d_in[10];
    const float* end_b    = (const float*)d_in[11];
    float* out = (float*)d_out;
    (void)in_sizes; (void)n_in; (void)out_size;

    int smem_conv = (3 * KC * 128 + KC * BSW) * (int)sizeof(float);  // 96 KB
    cudaFuncSetAttribute(layer_conv_kernel,
                         cudaFuncAttributeMaxDynamicSharedMemorySize, smem_conv);

    tr_inw_kernel<<<(NL * 512 * CH * 3 + 255) / 256, 256>>>(in_w);
    tr_rsw_kernel<<<(NL * 512 * CH + 255) / 256, 256>>>(rs_w);
    tr_cw_kernel<<<(NL * 512 * 80 + 255) / 256, 256>>>(cond_w);

    start_kernel<<<(B_N * CH * T_N) / 256, 256>>>(forecast, start_w, start_b);

    dim3 grid(T_N / TT, CH / 64, B_N);
    for (int li = 0; li < NL; li++) {
        layer_conv_kernel<<<grid, 256, smem_conv>>>(context, in_b, cond_b, li, DIL[li]);
        rs_kernel<<<grid, 256>>>(rs_b, li, li == NL - 1 ? 1 : 0);
    }

    end_kernel<<<(B_N * T_N) / 256, 256>>>(forecast, end_w, end_b, out);
}

// round 6
// speedup vs baseline: 1.5642x; 1.5642x over previous
#include <cuda_runtime.h>
#include <cuda_bf16.h>
#include <cstdint>

#define T_N 4096
#define B_N 8
#define NL  8

// ---------------- device scratch ----------------
__device__ __align__(16) float         g_x [B_N*T_N*256];
__device__ __align__(16) __nv_bfloat16 g_xh[B_N*T_N*256];
__device__ __align__(16) __nv_bfloat16 g_xl[B_N*T_N*256];
__device__ __align__(16) __nv_bfloat16 g_ah[B_N*T_N*256];
__device__ __align__(16) __nv_bfloat16 g_al[B_N*T_N*256];
__device__ __align__(16) float         g_oa[B_N*T_N*256];
__device__ __align__(16) __nv_bfloat16 g_ch[B_N*T_N*80];
__device__ __align__(16) __nv_bfloat16 g_cl[B_N*T_N*80];
__device__ __align__(16) __nv_bfloat16 g_wc[(size_t)NL*42*32768];  // conv img [li][q][jt][256][64]
__device__ __align__(16) __nv_bfloat16 g_wr[(size_t)NL*12*32768];  // rs img

// ---------------- helpers ----------------
__device__ __forceinline__ uint32_t smem_u32(const void* p) {
    uint32_t a;
    asm("{ .reg .u64 t; cvta.to.shared.u64 t, %1; cvt.u32.u64 %0, t; }" : "=r"(a) : "l"(p));
    return a;
}
__device__ __forceinline__ uint32_t swz(uint32_t x) { return x ^ ((x >> 3) & 0x70); }

#define CP16(dst, src, sz) \
    asm volatile("cp.async.ca.shared.global [%0], [%1], 16, %2;" \
        :: "r"(dst), "l"(src), "r"(sz) : "memory")
#define CPCOMMIT() asm volatile("cp.async.commit_group;" ::: "memory")
#define CPWAIT1()  asm volatile("cp.async.wait_group 1;" ::: "memory")
#define CPWAIT0()  asm volatile("cp.async.wait_group 0;" ::: "memory")

__device__ __forceinline__ void ldmx4(uint32_t* r, uint32_t a) {
    asm volatile("ldmatrix.sync.aligned.m8n8.x4.shared.b16 {%0,%1,%2,%3}, [%4];"
        : "=r"(r[0]), "=r"(r[1]), "=r"(r[2]), "=r"(r[3]) : "r"(a));
}
__device__ __forceinline__ void mma16816(float* c, const uint32_t* a, const uint32_t* b) {
    asm volatile("mma.sync.aligned.m16n8k16.row.col.f32.bf16.bf16.f32 "
        "{%0,%1,%2,%3}, {%4,%5,%6,%7}, {%8,%9}, {%0,%1,%2,%3};"
        : "+f"(c[0]), "+f"(c[1]), "+f"(c[2]), "+f"(c[3])
        : "r"(a[0]), "r"(a[1]), "r"(a[2]), "r"(a[3]), "r"(b[0]), "r"(b[1]));
}
__device__ __forceinline__ float sigf(float x) { return 1.f / (1.f + __expf(-x)); }

// ---------------- weight image prep ----------------
// conv img elem: li,q,jt,n(256),k(64). o = jt*128 + n/2; s=n&1; och = o + s*256.
// q<36: pp=q/4 -> tap=pp/3, split p=pp%3, c=(q%4)*64+k, w=in_w[och][c][tap]
// q>=36: p=(q-36)/2, m=((q-36)&1)*64+k (0 if m>=80), w=cond_w[och][m]
// value = (p==2) ? lo(w) : hi(w). stored pre-swizzled within 32KB (jt 16KB-half) tile.
__global__ void prep_conv_img(const float* __restrict__ in_w,
                              const float* __restrict__ cond_w) {
    int idx = blockIdx.x * 256 + threadIdx.x;
    if (idx >= NL * 42 * 32768) return;
    int li = idx / (42 * 32768);
    int r  = idx % (42 * 32768);
    int q = r >> 15, rr = r & 32767;
    int jt = rr >> 14, n = (rr >> 6) & 255, k = rr & 63;
    int o = jt * 128 + (n >> 1), s = n & 1;
    int och = o + s * 256;
    float w; int p;
    if (q < 36) {
        int pp = q >> 2; p = pp % 3;
        int tap = pp / 3, c = (q & 3) * 64 + k;
        w = in_w[((size_t)(li * 512 + och) * 256 + c) * 3 + tap];
    } else {
        int qq = q - 36; p = qq >> 1;
        int m = (qq & 1) * 64 + k;
        w = (m < 80) ? cond_w[(size_t)(li * 512 + och) * 80 + m] : 0.f;
    }
    __nv_bfloat16 h = __float2bfloat16(w);
    if (p == 2) h = __float2bfloat16(w - __bfloat162float(h));
    g_wc[(size_t)(li * 42 + q) * 32768 + jt * 16384 + (swz((uint32_t)n * 128 + k * 2) >> 1)] = h;
}

__global__ void prep_rs_img(const float* __restrict__ rs_w) {
    int idx = blockIdx.x * 256 + threadIdx.x;
    if (idx >= NL * 12 * 32768) return;
    int li = idx / (12 * 32768);
    int r  = idx % (12 * 32768);
    int q = r >> 15, rr = r & 32767;
    int jt = rr >> 14, n = (rr >> 6) & 255, k = rr & 63;
    int o = jt * 128 + (n >> 1), s = n & 1;
    int och = o + s * 256;
    int p = q >> 2, c = (q & 3) * 64 + k;
    float w = rs_w[(size_t)(li * 512 + och) * 256 + c];
    __nv_bfloat16 h = __float2bfloat16(w);
    if (p == 2) h = __float2bfloat16(w - __bfloat162float(h));
    g_wr[(size_t)(li * 12 + q) * 32768 + jt * 16384 + (swz((uint32_t)n * 128 + k * 2) >> 1)] = h;
}

// ---------------- context transpose+split: [b][m][t] -> [b][t][m] ----------------
__global__ void ctx_prep(const float* __restrict__ ctx) {
    __shared__ float tile[80][33];
    int b = blockIdx.y, t0 = blockIdx.x * 32, tid = threadIdx.x;
    int i = tid & 31, m0 = tid >> 5;
    for (int mm = m0; mm < 80; mm += 8)
        tile[mm][i] = ctx[((size_t)b * 80 + mm) * T_N + t0 + i];
    __syncthreads();
    int tt = tid >> 3, sg = tid & 7;
    size_t rb = ((size_t)b * T_N + t0 + tt) * 80;
    for (int e = 0; e < 10; e++) {
        int m = sg * 10 + e;
        float v = tile[m][tt];
        __nv_bfloat16 h = __float2bfloat16(v);
        g_ch[rb + m] = h;
        g_cl[rb + m] = __float2bfloat16(v - __bfloat162float(h));
    }
}

// ---------------- start conv (1x1, 4->256) ----------------
__global__ void start_k(const float* __restrict__ f, const float* __restrict__ sw,
                        const float* __restrict__ sb) {
    __shared__ float ft[4][128];
    int t0 = blockIdx.x * 128, b = blockIdx.y, c = threadIdx.x;
    for (int e = 0; e < 2; e++) {
        int idx = e * 256 + c;
        ft[idx >> 7][idx & 127] = f[((size_t)b * 8 + (idx >> 7)) * T_N + t0 + (idx & 127)];
    }
    float w0 = sw[c * 4], w1 = sw[c * 4 + 1], w2 = sw[c * 4 + 2], w3 = sw[c * 4 + 3];
    float bb = sb[c];
    __syncthreads();
    for (int t = 0; t < 128; t++) {
        float v = fmaf(ft[3][t], w3, fmaf(ft[2][t], w2, fmaf(ft[1][t], w1, fmaf(ft[0][t], w0, bb))));
        size_t o = ((size_t)b * T_N + t0 + t) * 256 + c;
        g_x[o] = v; g_oa[o] = 0.f;
        __nv_bfloat16 h = __float2bfloat16(v);
        g_xh[o] = h;
        g_xl[o] = __float2bfloat16(v - __bfloat162float(h));
    }
}

// ---------------- conv GEMM + gate (mma.sync) ----------------
// smem: A0 0, A1 16KB, B0 32KB, B1 64KB (96KB total)
__global__ __launch_bounds__(256) void conv_k(const float* __restrict__ ib_,
                                              const float* __restrict__ cb_,
                                              int li, int d) {
    extern __shared__ char sm[];
    uint32_t sb = smem_u32(sm);
    int tid = threadIdx.x, wid = tid >> 5, lane = tid & 31;
    int t0 = blockIdx.x * 128, jt = blockIdx.y, b = blockIdx.z;

    auto stageA = [&](int q, int buf) {
        uint32_t ad = sb + buf * 16384;
#pragma unroll
        for (int e = 0; e < 4; e++) {
            int idx = e * 256 + tid, row = idx >> 3, seg = idx & 7;
            const char* src; int sz = 16;
            if (q < 36) {
                int pp = q >> 2, p = pp % 3, tap = pp / 3, c0 = (q & 3) * 64;
                int t = t0 + row + (tap - 1) * d;
                if (t < 0 || t >= T_N) { src = (const char*)g_xh; sz = 0; }
                else src = (const char*)(((p == 1) ? g_xl : g_xh)
                           + ((size_t)(b * T_N + t) * 256 + c0)) + seg * 16;
            } else {
                int qq = q - 36, p = qq >> 1, hk = qq & 1;
                src = (const char*)(((p == 1) ? g_cl : g_ch)
                      + ((size_t)(b * T_N + t0 + row) * 80 + hk * 64)) + seg * 16;
                if (hk && seg >= 2) { src = (const char*)g_ch; sz = 0; }
            }
            CP16(ad + swz((uint32_t)row * 128 + seg * 16), src, sz);
        }
    };
    auto stageB = [&](int q, int buf) {
        const char* bsrc = (const char*)(g_wc + (size_t)(li * 42 + q) * 32768 + jt * 16384);
        uint32_t bd = sb + 32768 + buf * 32768;
#pragma unroll
        for (int e = 0; e < 8; e++) { int idx = e * 256 + tid; CP16(bd + idx * 16, bsrc + idx * 16, 16); }
    };

    float c[4][8][4];
#pragma unroll
    for (int i = 0; i < 4; i++)
#pragma unroll
        for (int j = 0; j < 8; j++)
#pragma unroll
            for (int k = 0; k < 4; k++) c[i][j][k] = 0.f;

    int mb = (wid & 1) * 64, nb = (wid >> 1) * 64;
    int rA = lane & 15, cA = (lane >> 4) * 16;
    int rB = ((lane >> 4) & 1) * 8 + (lane & 7), cB = ((lane >> 3) & 1) * 16;

    stageA(0, 0); stageB(0, 0); CPCOMMIT();
    stageA(1, 1); stageB(1, 1); CPCOMMIT();

    for (int q = 0; q < 42; q++) {
        int buf = q & 1;
        if (q == 41) CPWAIT0(); else CPWAIT1();
        __syncthreads();
        uint32_t aB = sb + buf * 16384, bB = sb + 32768 + buf * 32768;
#pragma unroll
        for (int ks = 0; ks < 4; ks++) {
            uint32_t af[4][4], bf[4][4];
#pragma unroll
            for (int mi = 0; mi < 4; mi++)
                ldmx4(af[mi], aB + swz((uint32_t)(mb + mi * 16 + rA) * 128 + ks * 32 + cA));
#pragma unroll
            for (int nj = 0; nj < 4; nj++)
                ldmx4(bf[nj], bB + swz((uint32_t)(nb + nj * 16 + rB) * 128 + ks * 32 + cB));
#pragma unroll
            for (int mi = 0; mi < 4; mi++)
#pragma unroll
                for (int nj = 0; nj < 4; nj++) {
                    mma16816(c[mi][nj * 2],     af[mi], &bf[nj][0]);
                    mma16816(c[mi][nj * 2 + 1], af[mi], &bf[nj][2]);
                }
        }
        __syncthreads();
        if (q + 2 < 42) { stageA(q + 2, buf); stageB(q + 2, buf); CPCOMMIT(); }
    }

    // epilogue: gate
    const float* ib = ib_ + li * 512;
    const float* cb = cb_ + li * 512;
    int qrow = lane >> 2, qcol = lane & 3;
#pragma unroll
    for (int nt = 0; nt < 8; nt++) {
        int o = jt * 128 + ((nb + nt * 8) >> 1) + qcol;
        float b1 = ib[o] + cb[o];
        float b2 = ib[o + 256] + cb[o + 256];
#pragma unroll
        for (int mi = 0; mi < 4; mi++) {
            int t = t0 + mb + mi * 16 + qrow;
            size_t i0 = ((size_t)(b * T_N + t)) * 256 + o;
            size_t i1 = i0 + 8 * 256;
            float a0 = tanhf(c[mi][nt][0] + b1) * sigf(c[mi][nt][1] + b2);
            float a1 = tanhf(c[mi][nt][2] + b1) * sigf(c[mi][nt][3] + b2);
            __nv_bfloat16 h0 = __float2bfloat16(a0);
            __nv_bfloat16 h1 = __float2bfloat16(a1);
            g_ah[i0] = h0; g_al[i0] = __float2bfloat16(a0 - __bfloat162float(h0));
            g_ah[i1] = h1; g_al[i1] = __float2bfloat16(a1 - __bfloat162float(h1));
        }
    }
}

// ---------------- rs GEMM + residual/skip (mma.sync) ----------------
__global__ __launch_bounds__(256) void rs_k(const float* __restrict__ rb_,
                                            int li, int last) {
    extern __shared__ char sm[];
    uint32_t sb = smem_u32(sm);
    int tid = threadIdx.x, wid = tid >> 5, lane = tid & 31;
    int t0 = blockIdx.x * 128, jt = blockIdx.y, b = blockIdx.z;

    auto stageA = [&](int q, int buf) {
        uint32_t ad = sb + buf * 16384;
        int p = q >> 2, c0 = (q & 3) * 64;
        const char* base = (const char*)(((p == 1) ? g_al : g_ah)
                            + ((size_t)(b * T_N + t0) * 256 + c0));
#pragma unroll
        for (int e = 0; e < 4; e++) {
            int idx = e * 256 + tid, row = idx >> 3, seg = idx & 7;
            CP16(ad + swz((uint32_t)row * 128 + seg * 16),
                 base + (size_t)row * 512 + seg * 16, 16);
        }
    };
    auto stageB = [&](int q, int buf) {
        const char* bsrc = (const char*)(g_wr + (size_t)(li * 12 + q) * 32768 + jt * 16384);
        uint32_t bd = sb + 32768 + buf * 32768;
#pragma unroll
        for (int e = 0; e < 8; e++) { int idx = e * 256 + tid; CP16(bd + idx * 16, bsrc + idx * 16, 16); }
    };

    float c[4][8][4];
#pragma unroll
    for (int i = 0; i < 4; i++)
#pragma unroll
        for (int j = 0; j < 8; j++)
#pragma unroll
            for (int k = 0; k < 4; k++) c[i][j][k] = 0.f;

    int mb = (wid & 1) * 64, nb = (wid >> 1) * 64;
    int rA = lane & 15, cA = (lane >> 4) * 16;
    int rB = ((lane >> 4) & 1) * 8 + (lane & 7), cB = ((lane >> 3) & 1) * 16;

    stageA(0, 0); stageB(0, 0); CPCOMMIT();
    stageA(1, 1); stageB(1, 1); CPCOMMIT();

    for (int q = 0; q < 12; q++) {
        int buf = q & 1;
        if (q == 11) CPWAIT0(); else CPWAIT1();
        __syncthreads();
        uint32_t aB = sb + buf * 16384, bB = sb + 32768 + buf * 32768;
#pragma unroll
        for (int ks = 0; ks < 4; ks++) {
            uint32_t af[4][4], bf[4][4];
#pragma unroll
            for (int mi = 0; mi < 4; mi++)
                ldmx4(af[mi], aB + swz((uint32_t)(mb + mi * 16 + rA) * 128 + ks * 32 + cA));
#pragma unroll
            for (int nj = 0; nj < 4; nj++)
                ldmx4(bf[nj], bB + swz((uint32_t)(nb + nj * 16 + rB) * 128 + ks * 32 + cB));
#pragma unroll
            for (int mi = 0; mi < 4; mi++)
#pragma unroll
                for (int nj = 0; nj < 4; nj++) {
                    mma16816(c[mi][nj * 2],     af[mi], &bf[nj][0]);
                    mma16816(c[mi][nj * 2 + 1], af[mi], &bf[nj][2]);
                }
        }
        __syncthreads();
        if (q + 2 < 12) { stageA(q + 2, buf); stageB(q + 2, buf); CPCOMMIT(); }
    }

    const float* rb = rb_ + li * 512;
    int qrow = lane >> 2, qcol = lane & 3;
#pragma unroll
    for (int nt = 0; nt < 8; nt++) {
        int o = jt * 128 + ((nb + nt * 8) >> 1) + qcol;
        float r1b = rb[o], r2b = rb[o + 256];
#pragma unroll
        for (int mi = 0; mi < 4; mi++) {
            int t = t0 + mb + mi * 16 + qrow;
            size_t i0 = ((size_t)(b * T_N + t)) * 256 + o;
            size_t i1 = i0 + 8 * 256;
            if (!last) {
                float v0 = g_x[i0] + c[mi][nt][0] + r1b;
                float v1 = g_x[i1] + c[mi][nt][2] + r1b;
                g_x[i0] = v0; g_x[i1] = v1;
                __nv_bfloat16 h0 = __float2bfloat16(v0);
                __nv_bfloat16 h1 = __float2bfloat16(v1);
                g_xh[i0] = h0; g_xl[i0] = __float2bfloat16(v0 - __bfloat162float(h0));
                g_xh[i1] = h1; g_xl[i1] = __float2bfloat16(v1 - __bfloat162float(h1));
                g_oa[i0] += c[mi][nt][1] + r2b;
                g_oa[i1] += c[mi][nt][3] + r2b;
            } else {
                g_oa[i0] += c[mi][nt][0] + r1b;
                g_oa[i1] += c[mi][nt][2] + r1b;
            }
        }
    }
}

// ---------------- end conv (1x1, 256->8) + affine ----------------
__global__ void end_k(const float* __restrict__ f, const float* __restrict__ ew,
                      const float* __restrict__ eb, float* __restrict__ out) {
    __shared__ float w[2048];
    int tid = threadIdx.x;
    for (int e = tid; e < 2048; e += 256) w[e] = ew[e];
    __syncthreads();
    int idx = blockIdx.x * 256 + tid;
    int t = idx & (T_N - 1), b = idx >> 12;
    float acc[8];
#pragma unroll
    for (int o = 0; o < 8; o++) acc[o] = eb[o];
    const float4* oa = (const float4*)(g_oa + (size_t)(b * T_N + t) * 256);
    for (int c4 = 0; c4 < 64; c4++) {
        float4 v = oa[c4];
#pragma unroll
        for (int o = 0; o < 8; o++) {
            acc[o] = fmaf(v.x, w[o * 256 + c4 * 4],     acc[o]);
            acc[o] = fmaf(v.y, w[o * 256 + c4 * 4 + 1], acc[o]);
            acc[o] = fmaf(v.z, w[o * 256 + c4 * 4 + 2], acc[o]);
            acc[o] = fmaf(v.w, w[o * 256 + c4 * 4 + 3], acc[o]);
        }
    }
    const float* fb = f + (size_t)b * 8 * T_N + t;
    float* cc = out + (size_t)b * 8 * T_N + t;
    float* lo = out + (size_t)B_N * 8 * T_N + (size_t)b * 4 * T_N + t;
#pragma unroll
    for (int l = 0; l < 4; l++) {
        cc[(size_t)l * T_N] = fb[(size_t)l * T_N];
        float ls = acc[4 + l];
        cc[(size_t)(4 + l) * T_N] = expf(ls) * fb[(size_t)(4 + l) * T_N] + acc[l];
        lo[(size_t)l * T_N] = ls;
    }
}

// ---------------- launch ----------------
static const int DIL[NL] = {1, 2, 4, 8, 16, 32, 64, 128};
#define GEMM_SMEM 98304

extern "C" void kernel_launch(void* const* d_in, const int* in_sizes, int n_in,
                              void* d_out, int out_size) {
    const float* forecast = (const float*)d_in[0];
    const float* context  = (const float*)d_in[1];
    const float* start_w  = (const float*)d_in[2];
    const float* start_b  = (const float*)d_in[3];
    const float* cond_w   = (const float*)d_in[4];
    const float* cond_b   = (const float*)d_in[5];
    const float* in_w     = (const float*)d_in[6];
    const float* in_b     = (const float*)d_in[7];
    const float* rs_w     = (const float*)d_in[8];
    const float* rs_b     = (const float*)d_in[9];
    const float* end_w    = (const float*)d_in[10];
    const float* end_b    = (const float*)d_in[11];
    float* out = (float*)d_out;
    (void)in_sizes; (void)n_in; (void)out_size;

    cudaFuncSetAttribute(conv_k, cudaFuncAttributeMaxDynamicSharedMemorySize, GEMM_SMEM);
    cudaFuncSetAttribute(rs_k,   cudaFuncAttributeMaxDynamicSharedMemorySize, GEMM_SMEM);

    prep_conv_img<<<(NL * 42 * 32768) / 256, 256>>>(in_w, cond_w);
    prep_rs_img<<<(NL * 12 * 32768) / 256, 256>>>(rs_w);
    ctx_prep<<<dim3(T_N / 32, B_N), 256>>>(context);
    start_k<<<dim3(T_N / 128, B_N), 256>>>(forecast, start_w, start_b);

    dim3 grid(T_N / 128, 2, B_N);
    for (int li = 0; li < NL; li++) {
        conv_k<<<grid, 256, GEMM_SMEM>>>(in_b, cond_b, li, DIL[li]);
        rs_k<<<grid, 256, GEMM_SMEM>>>(rs_b, li, li == NL - 1 ? 1 : 0);
    }
    end_k<<<(B_N * T_N) / 256, 256>>>(forecast, end_w, end_b, out);
}

// round 7
// speedup vs baseline: 1.7430x; 1.1143x over previous
#include <cuda_runtime.h>
#include <cuda_bf16.h>
#include <cstdint>

#define T_N 4096
#define B_N 8
#define NL  8
#define STG_B 49152          // per pipeline stage: 16KB A + 32KB B
#define GEMM_SMEM 147456     // 3 stages

// ---------------- device scratch ----------------
__device__ __align__(16) float         g_x [B_N*T_N*256];
__device__ __align__(16) __nv_bfloat16 g_xh[B_N*T_N*256];
__device__ __align__(16) __nv_bfloat16 g_xl[B_N*T_N*256];
__device__ __align__(16) __nv_bfloat16 g_ah[B_N*T_N*256];
__device__ __align__(16) __nv_bfloat16 g_al[B_N*T_N*256];
__device__ __align__(16) float         g_oa[B_N*T_N*256];
__device__ __align__(16) __nv_bfloat16 g_ch[B_N*T_N*80];
__device__ __align__(16) __nv_bfloat16 g_cl[B_N*T_N*80];
__device__ __align__(16) __nv_bfloat16 g_wc[(size_t)NL*42*32768];
__device__ __align__(16) __nv_bfloat16 g_wr[(size_t)NL*12*32768];

// ---------------- helpers ----------------
__device__ __forceinline__ uint32_t smem_u32(const void* p) {
    uint32_t a;
    asm("{ .reg .u64 t; cvta.to.shared.u64 t, %1; cvt.u32.u64 %0, t; }" : "=r"(a) : "l"(p));
    return a;
}
__device__ __forceinline__ uint32_t swz(uint32_t x) { return x ^ ((x >> 3) & 0x70); }

#define CP16(dst, src, sz) \
    asm volatile("cp.async.ca.shared.global [%0], [%1], 16, %2;" \
        :: "r"(dst), "l"(src), "r"(sz) : "memory")
#define CPCOMMIT() asm volatile("cp.async.commit_group;" ::: "memory")
#define CPWAIT1()  asm volatile("cp.async.wait_group 1;" ::: "memory")
#define CPWAIT0()  asm volatile("cp.async.wait_group 0;" ::: "memory")

__device__ __forceinline__ void ldmx4(uint32_t* r, uint32_t a) {
    asm volatile("ldmatrix.sync.aligned.m8n8.x4.shared.b16 {%0,%1,%2,%3}, [%4];"
        : "=r"(r[0]), "=r"(r[1]), "=r"(r[2]), "=r"(r[3]) : "r"(a));
}
__device__ __forceinline__ void mma16816(float* c, const uint32_t* a, const uint32_t* b) {
    asm volatile("mma.sync.aligned.m16n8k16.row.col.f32.bf16.bf16.f32 "
        "{%0,%1,%2,%3}, {%4,%5,%6,%7}, {%8,%9}, {%0,%1,%2,%3};"
        : "+f"(c[0]), "+f"(c[1]), "+f"(c[2]), "+f"(c[3])
        : "r"(a[0]), "r"(a[1]), "r"(a[2]), "r"(a[3]), "r"(b[0]), "r"(b[1]));
}
__device__ __forceinline__ float sigf(float x) { return 1.f / (1.f + __expf(-x)); }

// ---------------- merged weight-image prep ----------------
__global__ void prep_all(const float* __restrict__ in_w,
                         const float* __restrict__ cond_w,
                         const float* __restrict__ rs_w) {
    int idx = blockIdx.x * 256 + threadIdx.x;
    const int NC = NL * 42 * 32768;
    if (idx < NC) {
        int li = idx / (42 * 32768);
        int r  = idx % (42 * 32768);
        int q = r >> 15, rr = r & 32767;
        int jt = rr >> 14, n = (rr >> 6) & 255, k = rr & 63;
        int o = jt * 128 + (n >> 1), s = n & 1;
        int och = o + s * 256;
        float w; int p;
        if (q < 36) {
            int pp = q >> 2; p = pp % 3;
            int tap = pp / 3, c = (q & 3) * 64 + k;
            w = in_w[((size_t)(li * 512 + och) * 256 + c) * 3 + tap];
        } else {
            int qq = q - 36; p = qq >> 1;
            int m = (qq & 1) * 64 + k;
            w = (m < 80) ? cond_w[(size_t)(li * 512 + och) * 80 + m] : 0.f;
        }
        __nv_bfloat16 h = __float2bfloat16(w);
        if (p == 2) h = __float2bfloat16(w - __bfloat162float(h));
        g_wc[(size_t)(li * 42 + q) * 32768 + jt * 16384 + (swz((uint32_t)n * 128 + k * 2) >> 1)] = h;
    } else {
        idx -= NC;
        if (idx >= NL * 12 * 32768) return;
        int li = idx / (12 * 32768);
        int r  = idx % (12 * 32768);
        int q = r >> 15, rr = r & 32767;
        int jt = rr >> 14, n = (rr >> 6) & 255, k = rr & 63;
        int o = jt * 128 + (n >> 1), s = n & 1;
        int och = o + s * 256;
        int p = q >> 2, c = (q & 3) * 64 + k;
        float w = rs_w[(size_t)(li * 512 + och) * 256 + c];
        __nv_bfloat16 h = __float2bfloat16(w);
        if (p == 2) h = __float2bfloat16(w - __bfloat162float(h));
        g_wr[(size_t)(li * 12 + q) * 32768 + jt * 16384 + (swz((uint32_t)n * 128 + k * 2) >> 1)] = h;
    }
}

// ---------------- context transpose+split ----------------
__global__ void ctx_prep(const float* __restrict__ ctx) {
    __shared__ float tile[80][33];
    int b = blockIdx.y, t0 = blockIdx.x * 32, tid = threadIdx.x;
    int i = tid & 31, m0 = tid >> 5;
    for (int mm = m0; mm < 80; mm += 8)
        tile[mm][i] = ctx[((size_t)b * 80 + mm) * T_N + t0 + i];
    __syncthreads();
    int tt = tid >> 3, sg = tid & 7;
    size_t rb = ((size_t)b * T_N + t0 + tt) * 80;
    for (int e = 0; e < 10; e++) {
        int m = sg * 10 + e;
        float v = tile[m][tt];
        __nv_bfloat16 h = __float2bfloat16(v);
        g_ch[rb + m] = h;
        g_cl[rb + m] = __float2bfloat16(v - __bfloat162float(h));
    }
}

// ---------------- start conv ----------------
__global__ void start_k(const float* __restrict__ f, const float* __restrict__ sw,
                        const float* __restrict__ sb) {
    __shared__ float ft[4][128];
    int t0 = blockIdx.x * 128, b = blockIdx.y, c = threadIdx.x;
    for (int e = 0; e < 2; e++) {
        int idx = e * 256 + c;
        ft[idx >> 7][idx & 127] = f[((size_t)b * 8 + (idx >> 7)) * T_N + t0 + (idx & 127)];
    }
    float w0 = sw[c * 4], w1 = sw[c * 4 + 1], w2 = sw[c * 4 + 2], w3 = sw[c * 4 + 3];
    float bb = sb[c];
    __syncthreads();
    for (int t = 0; t < 128; t++) {
        float v = fmaf(ft[3][t], w3, fmaf(ft[2][t], w2, fmaf(ft[1][t], w1, fmaf(ft[0][t], w0, bb))));
        size_t o = ((size_t)b * T_N + t0 + t) * 256 + c;
        g_x[o] = v; g_oa[o] = 0.f;
        __nv_bfloat16 h = __float2bfloat16(v);
        g_xh[o] = h;
        g_xl[o] = __float2bfloat16(v - __bfloat162float(h));
    }
}

// ---------------- conv GEMM + gate ----------------
__global__ __launch_bounds__(256) void conv_k(const float* __restrict__ ib_,
                                              const float* __restrict__ cb_,
                                              int li, int d) {
    extern __shared__ char sm[];
    uint32_t sb = smem_u32(sm);
    int tid = threadIdx.x, wid = tid >> 5, lane = tid & 31;
    int t0 = blockIdx.x * 128, jt = blockIdx.y, b = blockIdx.z;

    // hoisted staging constants
    uint32_t adst[4]; long long abase[4]; int arow[4], aseg[4];
    long long cbase[4];
#pragma unroll
    for (int e = 0; e < 4; e++) {
        int idx = e * 256 + tid;
        int row = idx >> 3, seg = idx & 7;
        arow[e] = row; aseg[e] = seg;
        adst[e] = swz((uint32_t)row * 128 + seg * 16);
        abase[e] = (long long)((size_t)(b * T_N + t0 + row) * 256) * 2 + seg * 16;
        cbase[e] = (long long)((size_t)(b * T_N + t0 + row) * 80) * 2 + seg * 16;
    }

    auto stageA = [&](int q, int st) {
        uint32_t ad = sb + st * STG_B;
        if (q < 36) {
            int pp = q >> 2, p = pp % 3, tap = pp / 3, c0 = (q & 3) * 64;
            const char* bp = (const char*)((p == 1) ? g_xl : g_xh);
            long long sh = (long long)(tap - 1) * d * 512 + c0 * 2;
#pragma unroll
            for (int e = 0; e < 4; e++) {
                int t = t0 + arow[e] + (tap - 1) * d;
                int sz = (t >= 0 && t < T_N) ? 16 : 0;
                const char* src = sz ? (bp + abase[e] + sh) : bp;
                CP16(ad + adst[e], src, sz);
            }
        } else {
            int qq = q - 36, p = qq >> 1, hk = qq & 1;
            const char* bp = (const char*)((p == 1) ? g_cl : g_ch);
#pragma unroll
            for (int e = 0; e < 4; e++) {
                int sz = (!hk || aseg[e] < 2) ? 16 : 0;
                const char* src = sz ? (bp + cbase[e] + hk * 128) : bp;
                CP16(ad + adst[e], src, sz);
            }
        }
    };
    auto stageB = [&](int q, int st) {
        const char* bsrc = (const char*)(g_wc + (size_t)(li * 42 + q) * 32768 + jt * 16384);
        uint32_t bd = sb + st * STG_B + 16384;
#pragma unroll
        for (int e = 0; e < 8; e++) {
            int idx = e * 256 + tid;
            CP16(bd + idx * 16, bsrc + idx * 16, 16);
        }
    };

    float c[4][8][4];
#pragma unroll
    for (int i = 0; i < 4; i++)
#pragma unroll
        for (int j = 0; j < 8; j++)
#pragma unroll
            for (int k = 0; k < 4; k++) c[i][j][k] = 0.f;

    int mb = (wid & 1) * 64, nb = (wid >> 1) * 64;
    int rA = lane & 15, cA = (lane >> 4) * 16;
    int rB = ((lane >> 4) & 1) * 8 + (lane & 7), cB = ((lane >> 3) & 1) * 16;

    stageA(0, 0); stageB(0, 0); CPCOMMIT();
    stageA(1, 1); stageB(1, 1); CPCOMMIT();

    for (int q = 0; q < 42; q++) {
        int st = q % 3;
        if (q == 41) CPWAIT0(); else CPWAIT1();
        __syncthreads();
        if (q + 2 < 42) {
            int st2 = (q + 2) % 3;
            stageA(q + 2, st2); stageB(q + 2, st2); CPCOMMIT();
        }
        uint32_t aB = sb + st * STG_B, bB = aB + 16384;
#pragma unroll
        for (int ks = 0; ks < 4; ks++) {
            uint32_t af[4][4], bf[4][4];
#pragma unroll
            for (int mi = 0; mi < 4; mi++)
                ldmx4(af[mi], aB + swz((uint32_t)(mb + mi * 16 + rA) * 128 + ks * 32 + cA));
#pragma unroll
            for (int nj = 0; nj < 4; nj++)
                ldmx4(bf[nj], bB + swz((uint32_t)(nb + nj * 16 + rB) * 128 + ks * 32 + cB));
#pragma unroll
            for (int mi = 0; mi < 4; mi++)
#pragma unroll
                for (int nj = 0; nj < 4; nj++) {
                    mma16816(c[mi][nj * 2],     af[mi], &bf[nj][0]);
                    mma16816(c[mi][nj * 2 + 1], af[mi], &bf[nj][2]);
                }
        }
    }
    __syncthreads();

    // epilogue: gate -> smem tiles (pitch 136) -> coalesced global
    __nv_bfloat16* sh = (__nv_bfloat16*)sm;
    __nv_bfloat16* sl = (__nv_bfloat16*)(sm + 36864);
    const float* ib = ib_ + li * 512;
    const float* cb = cb_ + li * 512;
    int qrow = lane >> 2, qcol = lane & 3;
#pragma unroll
    for (int nt = 0; nt < 8; nt++) {
        int ol = (nb >> 1) + nt * 4 + qcol;
        int o = jt * 128 + ol;
        float b1 = ib[o] + cb[o];
        float b2 = ib[o + 256] + cb[o + 256];
#pragma unroll
        for (int mi = 0; mi < 4; mi++) {
            int tl = mb + mi * 16 + qrow;
            float a0 = tanhf(c[mi][nt][0] + b1) * sigf(c[mi][nt][1] + b2);
            float a1 = tanhf(c[mi][nt][2] + b1) * sigf(c[mi][nt][3] + b2);
            __nv_bfloat16 h0 = __float2bfloat16(a0);
            __nv_bfloat16 h1 = __float2bfloat16(a1);
            sh[tl * 136 + ol] = h0;
            sl[tl * 136 + ol] = __float2bfloat16(a0 - __bfloat162float(h0));
            sh[(tl + 8) * 136 + ol] = h1;
            sl[(tl + 8) * 136 + ol] = __float2bfloat16(a1 - __bfloat162float(h1));
        }
    }
    __syncthreads();
#pragma unroll
    for (int e = 0; e < 8; e++) {
        int idx = e * 256 + tid;
        int row = idx >> 4, sg = idx & 15;
        size_t go = (size_t)(b * T_N + t0 + row) * 256 + jt * 128;
        ((uint4*)(g_ah + go))[sg] = ((const uint4*)sh)[row * 17 + sg];
        ((uint4*)(g_al + go))[sg] = ((const uint4*)sl)[row * 17 + sg];
    }
}

// ---------------- rs GEMM + residual/skip ----------------
__global__ __launch_bounds__(256) void rs_k(const float* __restrict__ rb_,
                                            int li, int last) {
    extern __shared__ char sm[];
    uint32_t sb = smem_u32(sm);
    int tid = threadIdx.x, wid = tid >> 5, lane = tid & 31;
    int t0 = blockIdx.x * 128, jt = blockIdx.y, b = blockIdx.z;

    uint32_t adst[4]; long long abase[4];
#pragma unroll
    for (int e = 0; e < 4; e++) {
        int idx = e * 256 + tid;
        int row = idx >> 3, seg = idx & 7;
        adst[e] = swz((uint32_t)row * 128 + seg * 16);
        abase[e] = (long long)((size_t)(b * T_N + t0 + row) * 256) * 2 + seg * 16;
    }

    auto stageA = [&](int q, int st) {
        int p = q >> 2, c0 = (q & 3) * 64;
        const char* bp = (const char*)((p == 1) ? g_al : g_ah);
        uint32_t ad = sb + st * STG_B;
#pragma unroll
        for (int e = 0; e < 4; e++)
            CP16(ad + adst[e], bp + abase[e] + c0 * 2, 16);
    };
    auto stageB = [&](int q, int st) {
        const char* bsrc = (const char*)(g_wr + (size_t)(li * 12 + q) * 32768 + jt * 16384);
        uint32_t bd = sb + st * STG_B + 16384;
#pragma unroll
        for (int e = 0; e < 8; e++) {
            int idx = e * 256 + tid;
            CP16(bd + idx * 16, bsrc + idx * 16, 16);
        }
    };

    float c[4][8][4];
#pragma unroll
    for (int i = 0; i < 4; i++)
#pragma unroll
        for (int j = 0; j < 8; j++)
#pragma unroll
            for (int k = 0; k < 4; k++) c[i][j][k] = 0.f;

    int mb = (wid & 1) * 64, nb = (wid >> 1) * 64;
    int rA = lane & 15, cA = (lane >> 4) * 16;
    int rB = ((lane >> 4) & 1) * 8 + (lane & 7), cB = ((lane >> 3) & 1) * 16;

    stageA(0, 0); stageB(0, 0); CPCOMMIT();
    stageA(1, 1); stageB(1, 1); CPCOMMIT();

    for (int q = 0; q < 12; q++) {
        int st = q % 3;
        if (q == 11) CPWAIT0(); else CPWAIT1();
        __syncthreads();
        if (q + 2 < 12) {
            int st2 = (q + 2) % 3;
            stageA(q + 2, st2); stageB(q + 2, st2); CPCOMMIT();
        }
        uint32_t aB = sb + st * STG_B, bB = aB + 16384;
#pragma unroll
        for (int ks = 0; ks < 4; ks++) {
            uint32_t af[4][4], bf[4][4];
#pragma unroll
            for (int mi = 0; mi < 4; mi++)
                ldmx4(af[mi], aB + swz((uint32_t)(mb + mi * 16 + rA) * 128 + ks * 32 + cA));
#pragma unroll
            for (int nj = 0; nj < 4; nj++)
                ldmx4(bf[nj], bB + swz((uint32_t)(nb + nj * 16 + rB) * 128 + ks * 32 + cB));
#pragma unroll
            for (int mi = 0; mi < 4; mi++)
#pragma unroll
                for (int nj = 0; nj < 4; nj++) {
                    mma16816(c[mi][nj * 2],     af[mi], &bf[nj][0]);
                    mma16816(c[mi][nj * 2 + 1], af[mi], &bf[nj][2]);
                }
        }
    }
    __syncthreads();

    // epilogue via smem tiles (fp32, pitch 132)
    float* sr = (float*)sm;
    float* ss = (float*)(sm + 69632);
    int qrow = lane >> 2, qcol = lane & 3;
#pragma unroll
    for (int nt = 0; nt < 8; nt++) {
        int ol = (nb >> 1) + nt * 4 + qcol;
#pragma unroll
        for (int mi = 0; mi < 4; mi++) {
            int tl = mb + mi * 16 + qrow;
            sr[tl * 132 + ol] = c[mi][nt][0];
            ss[tl * 132 + ol] = c[mi][nt][1];
            sr[(tl + 8) * 132 + ol] = c[mi][nt][2];
            ss[(tl + 8) * 132 + ol] = c[mi][nt][3];
        }
    }
    __syncthreads();
    const float* rb = rb_ + li * 512;
#pragma unroll
    for (int e = 0; e < 16; e++) {
        int idx = e * 256 + tid;
        int row = idx >> 5, sg = idx & 31;
        int o = jt * 128 + sg * 4;
        size_t go = (size_t)(b * T_N + t0 + row) * 256 + o;
        float4 rv = ((const float4*)sr)[row * 33 + sg];
        float4 b1 = *(const float4*)(rb + o);
        if (!last) {
            float4 xv = *(const float4*)(g_x + go);
            float4 v = make_float4(xv.x + rv.x + b1.x, xv.y + rv.y + b1.y,
                                   xv.z + rv.z + b1.z, xv.w + rv.w + b1.w);
            *(float4*)(g_x + go) = v;
            __nv_bfloat16 h0 = __float2bfloat16(v.x), h1 = __float2bfloat16(v.y);
            __nv_bfloat16 h2 = __float2bfloat16(v.z), h3 = __float2bfloat16(v.w);
            __nv_bfloat162 hh0 = {h0, h1}, hh1 = {h2, h3};
            *(__nv_bfloat162*)(g_xh + go) = hh0;
            *(__nv_bfloat162*)(g_xh + go + 2) = hh1;
            __nv_bfloat162 ll0 = {__float2bfloat16(v.x - __bfloat162float(h0)),
                                  __float2bfloat16(v.y - __bfloat162float(h1))};
            __nv_bfloat162 ll1 = {__float2bfloat16(v.z - __bfloat162float(h2)),
                                  __float2bfloat16(v.w - __bfloat162float(h3))};
            *(__nv_bfloat162*)(g_xl + go) = ll0;
            *(__nv_bfloat162*)(g_xl + go + 2) = ll1;
            float4 sv = ((const float4*)ss)[row * 33 + sg];
            float4 b2 = *(const float4*)(rb + 256 + o);
            float4 ov = *(const float4*)(g_oa + go);
            ov.x += sv.x + b2.x; ov.y += sv.y + b2.y;
            ov.z += sv.z + b2.z; ov.w += sv.w + b2.w;
            *(float4*)(g_oa + go) = ov;
        } else {
            float4 ov = *(const float4*)(g_oa + go);
            ov.x += rv.x + b1.x; ov.y += rv.y + b1.y;
            ov.z += rv.z + b1.z; ov.w += rv.w + b1.w;
            *(float4*)(g_oa + go) = ov;
        }
    }
}

// ---------------- end conv + affine ----------------
__global__ void end_k(const float* __restrict__ f, const float* __restrict__ ew,
                      const float* __restrict__ eb, float* __restrict__ out) {
    __shared__ float w[2048];
    int tid = threadIdx.x;
    for (int e = tid; e < 2048; e += 256) w[e] = ew[e];
    __syncthreads();
    int idx = blockIdx.x * 256 + tid;
    int t = idx & (T_N - 1), b = idx >> 12;
    float acc[8];
#pragma unroll
    for (int o = 0; o < 8; o++) acc[o] = eb[o];
    const float4* oa = (const float4*)(g_oa + (size_t)(b * T_N + t) * 256);
    for (int c4 = 0; c4 < 64; c4++) {
        float4 v = oa[c4];
#pragma unroll
        for (int o = 0; o < 8; o++) {
            acc[o] = fmaf(v.x, w[o * 256 + c4 * 4],     acc[o]);
            acc[o] = fmaf(v.y, w[o * 256 + c4 * 4 + 1], acc[o]);
            acc[o] = fmaf(v.z, w[o * 256 + c4 * 4 + 2], acc[o]);
            acc[o] = fmaf(v.w, w[o * 256 + c4 * 4 + 3], acc[o]);
        }
    }
    const float* fb = f + (size_t)b * 8 * T_N + t;
    float* cc = out + (size_t)b * 8 * T_N + t;
    float* lo = out + (size_t)B_N * 8 * T_N + (size_t)b * 4 * T_N + t;
#pragma unroll
    for (int l = 0; l < 4; l++) {
        cc[(size_t)l * T_N] = fb[(size_t)l * T_N];
        float ls = acc[4 + l];
        cc[(size_t)(4 + l) * T_N] = expf(ls) * fb[(size_t)(4 + l) * T_N] + acc[l];
        lo[(size_t)l * T_N] = ls;
    }
}

// ---------------- launch ----------------
static const int DIL[NL] = {1, 2, 4, 8, 16, 32, 64, 128};

extern "C" void kernel_launch(void* const* d_in, const int* in_sizes, int n_in,
                              void* d_out, int out_size) {
    const float* forecast = (const float*)d_in[0];
    const float* context  = (const float*)d_in[1];
    const float* start_w  = (const float*)d_in[2];
    const float* start_b  = (const float*)d_in[3];
    const float* cond_w   = (const float*)d_in[4];
    const float* cond_b   = (const float*)d_in[5];
    const float* in_w     = (const float*)d_in[6];
    const float* in_b     = (const float*)d_in[7];
    const float* rs_w     = (const float*)d_in[8];
    const float* rs_b     = (const float*)d_in[9];
    const float* end_w    = (const float*)d_in[10];
    const float* end_b    = (const float*)d_in[11];
    float* out = (float*)d_out;
    (void)in_sizes; (void)n_in; (void)out_size;

    cudaFuncSetAttribute(conv_k, cudaFuncAttributeMaxDynamicSharedMemorySize, GEMM_SMEM);
    cudaFuncSetAttribute(rs_k,   cudaFuncAttributeMaxDynamicSharedMemorySize, GEMM_SMEM);

    prep_all<<<(NL * 54 * 32768) / 256, 256>>>(in_w, cond_w, rs_w);
    ctx_prep<<<dim3(T_N / 32, B_N), 256>>>(context);
    start_k<<<dim3(T_N / 128, B_N), 256>>>(forecast, start_w, start_b);

    dim3 grid(T_N / 128, 2, B_N);
    for (int li = 0; li < NL; li++) {
        conv_k<<<grid, 256, GEMM_SMEM>>>(in_b, cond_b, li, DIL[li]);
        rs_k<<<grid, 256, GEMM_SMEM>>>(rs_b, li, li == NL - 1 ? 1 : 0);
    }
    end_k<<<(B_N * T_N) / 256, 256>>>(forecast, end_w, end_b, out);
}

// round 8
// speedup vs baseline: 2.3055x; 1.3228x over previous
#include <cuda_runtime.h>
#include <cuda_bf16.h>
#include <cstdint>

#define T_N 4096
#define B_N 8
#define NL  8
#define STG_B 32768          // per stage: 16KB A + 16KB B
#define GEMM_SMEM 98304      // 3 stages

// ---------------- device scratch ----------------
__device__ __align__(16) float         g_x [B_N*T_N*256];
__device__ __align__(16) __nv_bfloat16 g_xh[B_N*T_N*256];
__device__ __align__(16) __nv_bfloat16 g_xl[B_N*T_N*256];
__device__ __align__(16) __nv_bfloat16 g_ah[B_N*T_N*256];
__device__ __align__(16) __nv_bfloat16 g_al[B_N*T_N*256];
__device__ __align__(16) float         g_oa[B_N*T_N*256];
__device__ __align__(16) __nv_bfloat16 g_ch[B_N*T_N*80];
__device__ __align__(16) __nv_bfloat16 g_cl[B_N*T_N*80];
__device__ __align__(16) __nv_bfloat16 g_wc[(size_t)NL*42*32768];
__device__ __align__(16) __nv_bfloat16 g_wr[(size_t)NL*12*32768];

// ---------------- helpers ----------------
__device__ __forceinline__ uint32_t smem_u32(const void* p) {
    uint32_t a;
    asm("{ .reg .u64 t; cvta.to.shared.u64 t, %1; cvt.u32.u64 %0, t; }" : "=r"(a) : "l"(p));
    return a;
}
__device__ __forceinline__ uint32_t swz(uint32_t x) { return x ^ ((x >> 3) & 0x70); }

#define CP16(dst, src, sz) \
    asm volatile("cp.async.ca.shared.global [%0], [%1], 16, %2;" \
        :: "r"(dst), "l"(src), "r"(sz) : "memory")
#define CPCOMMIT() asm volatile("cp.async.commit_group;" ::: "memory")
#define CPWAIT1()  asm volatile("cp.async.wait_group 1;" ::: "memory")
#define CPWAIT0()  asm volatile("cp.async.wait_group 0;" ::: "memory")

__device__ __forceinline__ void ldmx4(uint32_t* r, uint32_t a) {
    asm volatile("ldmatrix.sync.aligned.m8n8.x4.shared.b16 {%0,%1,%2,%3}, [%4];"
        : "=r"(r[0]), "=r"(r[1]), "=r"(r[2]), "=r"(r[3]) : "r"(a));
}
__device__ __forceinline__ void mma16816(float* c, const uint32_t* a, const uint32_t* b) {
    asm volatile("mma.sync.aligned.m16n8k16.row.col.f32.bf16.bf16.f32 "
        "{%0,%1,%2,%3}, {%4,%5,%6,%7}, {%8,%9}, {%0,%1,%2,%3};"
        : "+f"(c[0]), "+f"(c[1]), "+f"(c[2]), "+f"(c[3])
        : "r"(a[0]), "r"(a[1]), "r"(a[2]), "r"(a[3]), "r"(b[0]), "r"(b[1]));
}
__device__ __forceinline__ float sigf(float x) { return 1.f / (1.f + __expf(-x)); }

// ---------------- merged weight-image prep (16KB quarter tiles) ----------------
// per q tile: n_global(512) x k(64). jt4 = n>>7, nq = n&127.
// o = jt4*64 + nq/2, s = nq&1, och = o + s*256. value = (split p==2) ? lo : hi.
__global__ void prep_all(const float* __restrict__ in_w,
                         const float* __restrict__ cond_w,
                         const float* __restrict__ rs_w) {
    int idx = blockIdx.x * 256 + threadIdx.x;
    const int NC = NL * 42 * 32768;
    if (idx < NC) {
        int li = idx / (42 * 32768);
        int r  = idx % (42 * 32768);
        int q = r >> 15, rr = r & 32767;
        int ng = rr >> 6, k = rr & 63;
        int jt = ng >> 7, nq = ng & 127;
        int o = jt * 64 + (nq >> 1), s = nq & 1;
        int och = o + s * 256;
        float w; int p;
        if (q < 36) {
            int pp = q >> 2; p = pp % 3;
            int tap = pp / 3, c = (q & 3) * 64 + k;
            w = in_w[((size_t)(li * 512 + och) * 256 + c) * 3 + tap];
        } else {
            int qq = q - 36; p = qq >> 1;
            int m = (qq & 1) * 64 + k;
            w = (m < 80) ? cond_w[(size_t)(li * 512 + och) * 80 + m] : 0.f;
        }
        __nv_bfloat16 h = __float2bfloat16(w);
        if (p == 2) h = __float2bfloat16(w - __bfloat162float(h));
        g_wc[(size_t)(li * 42 + q) * 32768 + jt * 8192 + (swz((uint32_t)nq * 128 + k * 2) >> 1)] = h;
    } else {
        idx -= NC;
        if (idx >= NL * 12 * 32768) return;
        int li = idx / (12 * 32768);
        int r  = idx % (12 * 32768);
        int q = r >> 15, rr = r & 32767;
        int ng = rr >> 6, k = rr & 63;
        int jt = ng >> 7, nq = ng & 127;
        int o = jt * 64 + (nq >> 1), s = nq & 1;
        int och = o + s * 256;
        int p = q >> 2, c = (q & 3) * 64 + k;
        float w = rs_w[(size_t)(li * 512 + och) * 256 + c];
        __nv_bfloat16 h = __float2bfloat16(w);
        if (p == 2) h = __float2bfloat16(w - __bfloat162float(h));
        g_wr[(size_t)(li * 12 + q) * 32768 + jt * 8192 + (swz((uint32_t)nq * 128 + k * 2) >> 1)] = h;
    }
}

// ---------------- context transpose+split ----------------
__global__ void ctx_prep(const float* __restrict__ ctx) {
    __shared__ float tile[80][33];
    int b = blockIdx.y, t0 = blockIdx.x * 32, tid = threadIdx.x;
    int i = tid & 31, m0 = tid >> 5;
    for (int mm = m0; mm < 80; mm += 8)
        tile[mm][i] = ctx[((size_t)b * 80 + mm) * T_N + t0 + i];
    __syncthreads();
    int tt = tid >> 3, sg = tid & 7;
    size_t rb = ((size_t)b * T_N + t0 + tt) * 80;
    for (int e = 0; e < 10; e++) {
        int m = sg * 10 + e;
        float v = tile[m][tt];
        __nv_bfloat16 h = __float2bfloat16(v);
        g_ch[rb + m] = h;
        g_cl[rb + m] = __float2bfloat16(v - __bfloat162float(h));
    }
}

// ---------------- start conv ----------------
__global__ void start_k(const float* __restrict__ f, const float* __restrict__ sw,
                        const float* __restrict__ sb) {
    __shared__ float ft[4][128];
    int t0 = blockIdx.x * 128, b = blockIdx.y, c = threadIdx.x;
    for (int e = 0; e < 2; e++) {
        int idx = e * 256 + c;
        ft[idx >> 7][idx & 127] = f[((size_t)b * 8 + (idx >> 7)) * T_N + t0 + (idx & 127)];
    }
    float w0 = sw[c * 4], w1 = sw[c * 4 + 1], w2 = sw[c * 4 + 2], w3 = sw[c * 4 + 3];
    float bb = sb[c];
    __syncthreads();
    for (int t = 0; t < 128; t++) {
        float v = fmaf(ft[3][t], w3, fmaf(ft[2][t], w2, fmaf(ft[1][t], w1, fmaf(ft[0][t], w0, bb))));
        size_t o = ((size_t)b * T_N + t0 + t) * 256 + c;
        g_x[o] = v; g_oa[o] = 0.f;
        __nv_bfloat16 h = __float2bfloat16(v);
        g_xh[o] = h;
        g_xl[o] = __float2bfloat16(v - __bfloat162float(h));
    }
}

// ---------------- conv GEMM + gate (128t x 128n per CTA, 2 CTAs/SM) ----------------
__global__ __launch_bounds__(256, 2) void conv_k(const float* __restrict__ ib_,
                                                 const float* __restrict__ cb_,
                                                 int li, int d) {
    extern __shared__ char sm[];
    uint32_t sb = smem_u32(sm);
    int tid = threadIdx.x, wid = tid >> 5, lane = tid & 31;
    int t0 = blockIdx.x * 128, jt = blockIdx.y, b = blockIdx.z;

    // hoisted staging constants (A: 16KB = 4 cp16/thread)
    uint32_t adst[4]; long long abase[4]; int arow[4], aseg[4];
    long long cbase[4];
#pragma unroll
    for (int e = 0; e < 4; e++) {
        int idx = e * 256 + tid;
        int row = idx >> 3, seg = idx & 7;
        arow[e] = row; aseg[e] = seg;
        adst[e] = swz((uint32_t)row * 128 + seg * 16);
        abase[e] = (long long)((size_t)(b * T_N + t0 + row) * 256) * 2 + seg * 16;
        cbase[e] = (long long)((size_t)(b * T_N + t0 + row) * 80) * 2 + seg * 16;
    }

    auto stageA = [&](int q, int st) {
        uint32_t ad = sb + st * STG_B;
        if (q < 36) {
            int pp = q >> 2, p = pp % 3, tap = pp / 3, c0 = (q & 3) * 64;
            const char* bp = (const char*)((p == 1) ? g_xl : g_xh);
            long long sh = (long long)(tap - 1) * d * 512 + c0 * 2;
#pragma unroll
            for (int e = 0; e < 4; e++) {
                int t = t0 + arow[e] + (tap - 1) * d;
                int sz = (t >= 0 && t < T_N) ? 16 : 0;
                const char* src = sz ? (bp + abase[e] + sh) : bp;
                CP16(ad + adst[e], src, sz);
            }
        } else {
            int qq = q - 36, p = qq >> 1, hk = qq & 1;
            const char* bp = (const char*)((p == 1) ? g_cl : g_ch);
#pragma unroll
            for (int e = 0; e < 4; e++) {
                int sz = (!hk || aseg[e] < 2) ? 16 : 0;
                const char* src = sz ? (bp + cbase[e] + hk * 128) : bp;
                CP16(ad + adst[e], src, sz);
            }
        }
    };
    auto stageB = [&](int q, int st) {
        const char* bsrc = (const char*)(g_wc + (size_t)(li * 42 + q) * 32768 + jt * 8192);
        uint32_t bd = sb + st * STG_B + 16384;
#pragma unroll
        for (int e = 0; e < 4; e++) {
            int idx = e * 256 + tid;
            CP16(bd + idx * 16, bsrc + idx * 16, 16);
        }
    };

    float c[2][8][4];
#pragma unroll
    for (int i = 0; i < 2; i++)
#pragma unroll
        for (int j = 0; j < 8; j++)
#pragma unroll
            for (int k = 0; k < 4; k++) c[i][j][k] = 0.f;

    int mb = (wid & 3) * 32, nb = (wid >> 2) * 64;
    int rA = lane & 15, cA = (lane >> 4) * 16;
    int rB = ((lane >> 4) & 1) * 8 + (lane & 7), cB = ((lane >> 3) & 1) * 16;

    stageA(0, 0); stageB(0, 0); CPCOMMIT();
    stageA(1, 1); stageB(1, 1); CPCOMMIT();

    for (int q = 0; q < 42; q++) {
        int st = q % 3;
        if (q == 41) CPWAIT0(); else CPWAIT1();
        __syncthreads();
        if (q + 2 < 42) {
            int st2 = (q + 2) % 3;
            stageA(q + 2, st2); stageB(q + 2, st2); CPCOMMIT();
        }
        uint32_t aB = sb + st * STG_B, bB = aB + 16384;
#pragma unroll
        for (int ks = 0; ks < 4; ks++) {
            uint32_t af[2][4], bf[4][4];
#pragma unroll
            for (int mi = 0; mi < 2; mi++)
                ldmx4(af[mi], aB + swz((uint32_t)(mb + mi * 16 + rA) * 128 + ks * 32 + cA));
#pragma unroll
            for (int nj = 0; nj < 4; nj++)
                ldmx4(bf[nj], bB + swz((uint32_t)(nb + nj * 16 + rB) * 128 + ks * 32 + cB));
#pragma unroll
            for (int mi = 0; mi < 2; mi++)
#pragma unroll
                for (int nj = 0; nj < 4; nj++) {
                    mma16816(c[mi][nj * 2],     af[mi], &bf[nj][0]);
                    mma16816(c[mi][nj * 2 + 1], af[mi], &bf[nj][2]);
                }
        }
    }
    __syncthreads();

    // epilogue: gate -> smem tiles (64 cols, pitch 72 bf16) -> coalesced global
    __nv_bfloat16* shh = (__nv_bfloat16*)sm;
    __nv_bfloat16* sll = (__nv_bfloat16*)(sm + 20480);
    const float* ib = ib_ + li * 512;
    const float* cb = cb_ + li * 512;
    int qrow = lane >> 2, qcol = lane & 3;
#pragma unroll
    for (int nt = 0; nt < 8; nt++) {
        int ol = (nb >> 1) + nt * 4 + qcol;      // 0..63
        int o = jt * 64 + ol;
        float b1 = ib[o] + cb[o];
        float b2 = ib[o + 256] + cb[o + 256];
#pragma unroll
        for (int mi = 0; mi < 2; mi++) {
            int tl = mb + mi * 16 + qrow;
            float a0 = tanhf(c[mi][nt][0] + b1) * sigf(c[mi][nt][1] + b2);
            float a1 = tanhf(c[mi][nt][2] + b1) * sigf(c[mi][nt][3] + b2);
            __nv_bfloat16 h0 = __float2bfloat16(a0);
            __nv_bfloat16 h1 = __float2bfloat16(a1);
            shh[tl * 72 + ol] = h0;
            sll[tl * 72 + ol] = __float2bfloat16(a0 - __bfloat162float(h0));
            shh[(tl + 8) * 72 + ol] = h1;
            sll[(tl + 8) * 72 + ol] = __float2bfloat16(a1 - __bfloat162float(h1));
        }
    }
    __syncthreads();
#pragma unroll
    for (int e = 0; e < 4; e++) {
        int idx = e * 256 + tid;
        int row = idx >> 3, sg = idx & 7;
        size_t go = (size_t)(b * T_N + t0 + row) * 256 + jt * 64;
        ((uint4*)(g_ah + go))[sg] = ((const uint4*)shh)[row * 9 + sg];
        ((uint4*)(g_al + go))[sg] = ((const uint4*)sll)[row * 9 + sg];
    }
}

// ---------------- rs GEMM + residual/skip ----------------
__global__ __launch_bounds__(256, 2) void rs_k(const float* __restrict__ rb_,
                                               int li, int last) {
    extern __shared__ char sm[];
    uint32_t sb = smem_u32(sm);
    int tid = threadIdx.x, wid = tid >> 5, lane = tid & 31;
    int t0 = blockIdx.x * 128, jt = blockIdx.y, b = blockIdx.z;

    uint32_t adst[4]; long long abase[4];
#pragma unroll
    for (int e = 0; e < 4; e++) {
        int idx = e * 256 + tid;
        int row = idx >> 3, seg = idx & 7;
        adst[e] = swz((uint32_t)row * 128 + seg * 16);
        abase[e] = (long long)((size_t)(b * T_N + t0 + row) * 256) * 2 + seg * 16;
    }

    auto stageA = [&](int q, int st) {
        int p = q >> 2, c0 = (q & 3) * 64;
        const char* bp = (const char*)((p == 1) ? g_al : g_ah);
        uint32_t ad = sb + st * STG_B;
#pragma unroll
        for (int e = 0; e < 4; e++)
            CP16(ad + adst[e], bp + abase[e] + c0 * 2, 16);
    };
    auto stageB = [&](int q, int st) {
        const char* bsrc = (const char*)(g_wr + (size_t)(li * 12 + q) * 32768 + jt * 8192);
        uint32_t bd = sb + st * STG_B + 16384;
#pragma unroll
        for (int e = 0; e < 4; e++) {
            int idx = e * 256 + tid;
            CP16(bd + idx * 16, bsrc + idx * 16, 16);
        }
    };

    float c[2][8][4];
#pragma unroll
    for (int i = 0; i < 2; i++)
#pragma unroll
        for (int j = 0; j < 8; j++)
#pragma unroll
            for (int k = 0; k < 4; k++) c[i][j][k] = 0.f;

    int mb = (wid & 3) * 32, nb = (wid >> 2) * 64;
    int rA = lane & 15, cA = (lane >> 4) * 16;
    int rB = ((lane >> 4) & 1) * 8 + (lane & 7), cB = ((lane >> 3) & 1) * 16;

    stageA(0, 0); stageB(0, 0); CPCOMMIT();
    stageA(1, 1); stageB(1, 1); CPCOMMIT();

    for (int q = 0; q < 12; q++) {
        int st = q % 3;
        if (q == 11) CPWAIT0(); else CPWAIT1();
        __syncthreads();
        if (q + 2 < 12) {
            int st2 = (q + 2) % 3;
            stageA(q + 2, st2); stageB(q + 2, st2); CPCOMMIT();
        }
        uint32_t aB = sb + st * STG_B, bB = aB + 16384;
#pragma unroll
        for (int ks = 0; ks < 4; ks++) {
            uint32_t af[2][4], bf[4][4];
#pragma unroll
            for (int mi = 0; mi < 2; mi++)
                ldmx4(af[mi], aB + swz((uint32_t)(mb + mi * 16 + rA) * 128 + ks * 32 + cA));
#pragma unroll
            for (int nj = 0; nj < 4; nj++)
                ldmx4(bf[nj], bB + swz((uint32_t)(nb + nj * 16 + rB) * 128 + ks * 32 + cB));
#pragma unroll
            for (int mi = 0; mi < 2; mi++)
#pragma unroll
                for (int nj = 0; nj < 4; nj++) {
                    mma16816(c[mi][nj * 2],     af[mi], &bf[nj][0]);
                    mma16816(c[mi][nj * 2 + 1], af[mi], &bf[nj][2]);
                }
        }
    }
    __syncthreads();

    // epilogue via smem tiles (fp32, 64 cols, pitch 68)
    float* sr = (float*)sm;
    float* ss = (float*)(sm + 34816);
    int qrow = lane >> 2, qcol = lane & 3;
#pragma unroll
    for (int nt = 0; nt < 8; nt++) {
        int ol = (nb >> 1) + nt * 4 + qcol;
#pragma unroll
        for (int mi = 0; mi < 2; mi++) {
            int tl = mb + mi * 16 + qrow;
            sr[tl * 68 + ol] = c[mi][nt][0];
            ss[tl * 68 + ol] = c[mi][nt][1];
            sr[(tl + 8) * 68 + ol] = c[mi][nt][2];
            ss[(tl + 8) * 68 + ol] = c[mi][nt][3];
        }
    }
    __syncthreads();
    const float* rb = rb_ + li * 512;
#pragma unroll
    for (int e = 0; e < 8; e++) {
        int idx = e * 256 + tid;
        int row = idx >> 4, sg = idx & 15;
        int o = jt * 64 + sg * 4;
        size_t go = (size_t)(b * T_N + t0 + row) * 256 + o;
        float4 rv = ((const float4*)sr)[row * 17 + sg];
        float4 b1 = *(const float4*)(rb + o);
        if (!last) {
            float4 xv = *(const float4*)(g_x + go);
            float4 v = make_float4(xv.x + rv.x + b1.x, xv.y + rv.y + b1.y,
                                   xv.z + rv.z + b1.z, xv.w + rv.w + b1.w);
            *(float4*)(g_x + go) = v;
            __nv_bfloat16 h0 = __float2bfloat16(v.x), h1 = __float2bfloat16(v.y);
            __nv_bfloat16 h2 = __float2bfloat16(v.z), h3 = __float2bfloat16(v.w);
            __nv_bfloat162 hh0 = {h0, h1}, hh1 = {h2, h3};
            *(__nv_bfloat162*)(g_xh + go) = hh0;
            *(__nv_bfloat162*)(g_xh + go + 2) = hh1;
            __nv_bfloat162 ll0 = {__float2bfloat16(v.x - __bfloat162float(h0)),
                                  __float2bfloat16(v.y - __bfloat162float(h1))};
            __nv_bfloat162 ll1 = {__float2bfloat16(v.z - __bfloat162float(h2)),
                                  __float2bfloat16(v.w - __bfloat162float(h3))};
            *(__nv_bfloat162*)(g_xl + go) = ll0;
            *(__nv_bfloat162*)(g_xl + go + 2) = ll1;
            float4 sv = ((const float4*)ss)[row * 17 + sg];
            float4 b2 = *(const float4*)(rb + 256 + o);
            float4 ov = *(const float4*)(g_oa + go);
            ov.x += sv.x + b2.x; ov.y += sv.y + b2.y;
            ov.z += sv.z + b2.z; ov.w += sv.w + b2.w;
            *(float4*)(g_oa + go) = ov;
        } else {
            float4 ov = *(const float4*)(g_oa + go);
            ov.x += rv.x + b1.x; ov.y += rv.y + b1.y;
            ov.z += rv.z + b1.z; ov.w += rv.w + b1.w;
            *(float4*)(g_oa + go) = ov;
        }
    }
}

// ---------------- end conv + affine ----------------
__global__ void end_k(const float* __restrict__ f, const float* __restrict__ ew,
                      const float* __restrict__ eb, float* __restrict__ out) {
    __shared__ float w[2048];
    int tid = threadIdx.x;
    for (int e = tid; e < 2048; e += 256) w[e] = ew[e];
    __syncthreads();
    int idx = blockIdx.x * 256 + tid;
    int t = idx & (T_N - 1), b = idx >> 12;
    float acc[8];
#pragma unroll
    for (int o = 0; o < 8; o++) acc[o] = eb[o];
    const float4* oa = (const float4*)(g_oa + (size_t)(b * T_N + t) * 256);
    for (int c4 = 0; c4 < 64; c4++) {
        float4 v = oa[c4];
#pragma unroll
        for (int o = 0; o < 8; o++) {
            acc[o] = fmaf(v.x, w[o * 256 + c4 * 4],     acc[o]);
            acc[o] = fmaf(v.y, w[o * 256 + c4 * 4 + 1], acc[o]);
            acc[o] = fmaf(v.z, w[o * 256 + c4 * 4 + 2], acc[o]);
            acc[o] = fmaf(v.w, w[o * 256 + c4 * 4 + 3], acc[o]);
        }
    }
    const float* fb = f + (size_t)b * 8 * T_N + t;
    float* cc = out + (size_t)b * 8 * T_N + t;
    float* lo = out + (size_t)B_N * 8 * T_N + (size_t)b * 4 * T_N + t;
#pragma unroll
    for (int l = 0; l < 4; l++) {
        cc[(size_t)l * T_N] = fb[(size_t)l * T_N];
        float ls = acc[4 + l];
        cc[(size_t)(4 + l) * T_N] = expf(ls) * fb[(size_t)(4 + l) * T_N] + acc[l];
        lo[(size_t)l * T_N] = ls;
    }
}

// ---------------- launch ----------------
static const int DIL[NL] = {1, 2, 4, 8, 16, 32, 64, 128};

extern "C" void kernel_launch(void* const* d_in, const int* in_sizes, int n_in,
                              void* d_out, int out_size) {
    const float* forecast = (const float*)d_in[0];
    const float* context  = (const float*)d_in[1];
    const float* start_w  = (const float*)d_in[2];
    const float* start_b  = (const float*)d_in[3];
    const float* cond_w   = (const float*)d_in[4];
    const float* cond_b   = (const float*)d_in[5];
    const float* in_w     = (const float*)d_in[6];
    const float* in_b     = (const float*)d_in[7];
    const float* rs_w     = (const float*)d_in[8];
    const float* rs_b     = (const float*)d_in[9];
    const float* end_w    = (const float*)d_in[10];
    const float* end_b    = (const float*)d_in[11];
    float* out = (float*)d_out;
    (void)in_sizes; (void)n_in; (void)out_size;

    cudaFuncSetAttribute(conv_k, cudaFuncAttributeMaxDynamicSharedMemorySize, GEMM_SMEM);
    cudaFuncSetAttribute(rs_k,   cudaFuncAttributeMaxDynamicSharedMemorySize, GEMM_SMEM);

    prep_all<<<(NL * 54 * 32768) / 256, 256>>>(in_w, cond_w, rs_w);
    ctx_prep<<<dim3(T_N / 32, B_N), 256>>>(context);
    start_k<<<dim3(T_N / 128, B_N), 256>>>(forecast, start_w, start_b);

    dim3 grid(T_N / 128, 4, B_N);
    for (int li = 0; li < NL; li++) {
        conv_k<<<grid, 256, GEMM_SMEM>>>(in_b, cond_b, li, DIL[li]);
        rs_k<<<grid, 256, GEMM_SMEM>>>(rs_b, li, li == NL - 1 ? 1 : 0);
    }
    end_k<<<(B_N * T_N) / 256, 256>>>(forecast, end_w, end_b, out);
}

// round 10
// speedup vs baseline: 2.6251x; 1.1386x over previous
#include <cuda_runtime.h>
#include <cuda_bf16.h>
#include <cstdint>

#define T_N 4096
#define B_N 8
#define NL  8
#define NQC 40               // conv chunks: 36 x-parts + 4 packed ctx (240 slots)
#define STG_B 32768          // per stage: 16KB A + 16KB B
#define GEMM_SMEM 98304      // 3 stages

// ---------------- device scratch ----------------
__device__ __align__(16) float         g_x [B_N*T_N*256];
__device__ __align__(16) __nv_bfloat16 g_xh[B_N*T_N*256];
__device__ __align__(16) __nv_bfloat16 g_xl[B_N*T_N*256];
__device__ __align__(16) __nv_bfloat16 g_ah[B_N*T_N*256];
__device__ __align__(16) __nv_bfloat16 g_al[B_N*T_N*256];
__device__ __align__(16) float         g_oa[B_N*T_N*256];
__device__ __align__(16) __nv_bfloat16 g_ch[B_N*T_N*80];
__device__ __align__(16) __nv_bfloat16 g_cl[B_N*T_N*80];
__device__ __align__(16) __nv_bfloat16 g_wc[(size_t)NL*NQC*32768];
__device__ __align__(16) __nv_bfloat16 g_wr[(size_t)NL*12*32768];

// ---------------- helpers ----------------
__device__ __forceinline__ uint32_t smem_u32(const void* p) {
    uint32_t a;
    asm("{ .reg .u64 t; cvta.to.shared.u64 t, %1; cvt.u32.u64 %0, t; }" : "=r"(a) : "l"(p));
    return a;
}
__device__ __forceinline__ uint32_t swz(uint32_t x) { return x ^ ((x >> 3) & 0x70); }

#define CP16(dst, src, sz) \
    asm volatile("cp.async.cg.shared.global [%0], [%1], 16, %2;" \
        :: "r"(dst), "l"(src), "r"(sz) : "memory")
#define CPCOMMIT() asm volatile("cp.async.commit_group;" ::: "memory")
#define CPWAIT1()  asm volatile("cp.async.wait_group 1;" ::: "memory")
#define CPWAIT0()  asm volatile("cp.async.wait_group 0;" ::: "memory")

__device__ __forceinline__ void ldmx4(uint32_t* r, uint32_t a) {
    asm volatile("ldmatrix.sync.aligned.m8n8.x4.shared.b16 {%0,%1,%2,%3}, [%4];"
        : "=r"(r[0]), "=r"(r[1]), "=r"(r[2]), "=r"(r[3]) : "r"(a));
}
__device__ __forceinline__ void mma16816(float* c, const uint32_t* a, const uint32_t* b) {
    asm volatile("mma.sync.aligned.m16n8k16.row.col.f32.bf16.bf16.f32 "
        "{%0,%1,%2,%3}, {%4,%5,%6,%7}, {%8,%9}, {%0,%1,%2,%3};"
        : "+f"(c[0]), "+f"(c[1]), "+f"(c[2]), "+f"(c[3])
        : "r"(a[0]), "r"(a[1]), "r"(a[2]), "r"(a[3]), "r"(b[0]), "r"(b[1]));
}
__device__ __forceinline__ float sigf(float x) { return 1.f / (1.f + __expf(-x)); }

// ---------------- merged weight-image prep (16KB quarter tiles) ----------------
// per q tile: n_global(512) x k(64). jt4 = n>>7, nq = n&127.
// o = jt4*64 + nq/2, s = nq&1, och = o + s*256.
// q<36: x parts (tap, split).
// q in 36..39: packed ctx, linear slot sidx=(q-36)*64+k:
//   sidx<80:        A=ctx_hi[sidx],      W=hi(cond)      (ch*wh)
//   80<=sidx<160:   A=ctx_lo[sidx-80],   W=hi(cond)      (cl*wh)
//   160<=sidx<240:  A=ctx_hi[sidx-160],  W=lo(cond)      (ch*wl)
//   sidx>=240: zero
__global__ void prep_all(const float* __restrict__ in_w,
                         const float* __restrict__ cond_w,
                         const float* __restrict__ rs_w) {
    int idx = blockIdx.x * 256 + threadIdx.x;
    const int NC = NL * NQC * 32768;
    if (idx < NC) {
        int li = idx / (NQC * 32768);
        int r  = idx % (NQC * 32768);
        int q = r >> 15, rr = r & 32767;
        int ng = rr >> 6, k = rr & 63;
        int jt = ng >> 7, nq = ng & 127;
        int o = jt * 64 + (nq >> 1), s = nq & 1;
        int och = o + s * 256;
        float w; int p;
        if (q < 36) {
            int pp = q >> 2; p = pp % 3;
            int tap = pp / 3, c = (q & 3) * 64 + k;
            w = in_w[((size_t)(li * 512 + och) * 256 + c) * 3 + tap];
        } else {
            int sidx = (q - 36) * 64 + k;
            if (sidx < 80)       { w = cond_w[(size_t)(li * 512 + och) * 80 + sidx];        p = 0; }
            else if (sidx < 160) { w = cond_w[(size_t)(li * 512 + och) * 80 + sidx - 80];   p = 0; }
            else if (sidx < 240) { w = cond_w[(size_t)(li * 512 + och) * 80 + sidx - 160];  p = 2; }
            else                 { w = 0.f; p = 0; }
        }
        __nv_bfloat16 h = __float2bfloat16(w);
        if (p == 2) h = __float2bfloat16(w - __bfloat162float(h));
        g_wc[(size_t)(li * NQC + q) * 32768 + jt * 8192 + (swz((uint32_t)nq * 128 + k * 2) >> 1)] = h;
    } else {
        idx -= NC;
        if (idx >= NL * 12 * 32768) return;
        int li = idx / (12 * 32768);
        int r  = idx % (12 * 32768);
        int q = r >> 15, rr = r & 32767;
        int ng = rr >> 6, k = rr & 63;
        int jt = ng >> 7, nq = ng & 127;
        int o = jt * 64 + (nq >> 1), s = nq & 1;
        int och = o + s * 256;
        int p = q >> 2, c = (q & 3) * 64 + k;
        float w = rs_w[(size_t)(li * 512 + och) * 256 + c];
        __nv_bfloat16 h = __float2bfloat16(w);
        if (p == 2) h = __float2bfloat16(w - __bfloat162float(h));
        g_wr[(size_t)(li * 12 + q) * 32768 + jt * 8192 + (swz((uint32_t)nq * 128 + k * 2) >> 1)] = h;
    }
}

// ---------------- context transpose+split ----------------
__global__ void ctx_prep(const float* __restrict__ ctx) {
    __shared__ float tile[80][33];
    int b = blockIdx.y, t0 = blockIdx.x * 32, tid = threadIdx.x;
    int i = tid & 31, m0 = tid >> 5;
    for (int mm = m0; mm < 80; mm += 8)
        tile[mm][i] = ctx[((size_t)b * 80 + mm) * T_N + t0 + i];
    __syncthreads();
    int tt = tid >> 3, sg = tid & 7;
    size_t rb = ((size_t)b * T_N + t0 + tt) * 80;
    for (int e = 0; e < 10; e++) {
        int m = sg * 10 + e;
        float v = tile[m][tt];
        __nv_bfloat16 h = __float2bfloat16(v);
        g_ch[rb + m] = h;
        g_cl[rb + m] = __float2bfloat16(v - __bfloat162float(h));
    }
}

// ---------------- start conv ----------------
__global__ void start_k(const float* __restrict__ f, const float* __restrict__ sw,
                        const float* __restrict__ sb) {
    __shared__ float ft[4][128];
    int t0 = blockIdx.x * 128, b = blockIdx.y, c = threadIdx.x;
    for (int e = 0; e < 2; e++) {
        int idx = e * 256 + c;
        ft[idx >> 7][idx & 127] = f[((size_t)b * 8 + (idx >> 7)) * T_N + t0 + (idx & 127)];
    }
    float w0 = sw[c * 4], w1 = sw[c * 4 + 1], w2 = sw[c * 4 + 2], w3 = sw[c * 4 + 3];
    float bb = sb[c];
    __syncthreads();
    for (int t = 0; t < 128; t++) {
        float v = fmaf(ft[3][t], w3, fmaf(ft[2][t], w2, fmaf(ft[1][t], w1, fmaf(ft[0][t], w0, bb))));
        size_t o = ((size_t)b * T_N + t0 + t) * 256 + c;
        g_x[o] = v; g_oa[o] = 0.f;
        __nv_bfloat16 h = __float2bfloat16(v);
        g_xh[o] = h;
        g_xl[o] = __float2bfloat16(v - __bfloat162float(h));
    }
}

// ---------------- conv GEMM + gate (128t x 128n per CTA, 2 CTAs/SM) ----------------
__global__ __launch_bounds__(256, 2) void conv_k(const float* __restrict__ ib_,
                                                 const float* __restrict__ cb_,
                                                 int li, int d) {
    extern __shared__ char sm[];
    uint32_t sb = smem_u32(sm);
    int tid = threadIdx.x, wid = tid >> 5, lane = tid & 31;
    int t0 = blockIdx.x * 128, jt = blockIdx.y, b = blockIdx.z;

    // hoisted staging constants (A: 16KB = 4 cp16/thread)
    uint32_t adst[4]; long long abase[4]; int arow[4], aseg[4];
    long long crow[4];
#pragma unroll
    for (int e = 0; e < 4; e++) {
        int idx = e * 256 + tid;
        int row = idx >> 3, seg = idx & 7;
        arow[e] = row; aseg[e] = seg;
        adst[e] = swz((uint32_t)row * 128 + seg * 16);
        abase[e] = (long long)((size_t)(b * T_N + t0 + row) * 256) * 2 + seg * 16;
        crow[e]  = (long long)((size_t)(b * T_N + t0 + row) * 80) * 2;
    }

    auto stageA = [&](int q, int st) {
        uint32_t ad = sb + st * STG_B;
        if (q < 36) {
            int pp = q >> 2, p = pp % 3, tap = pp / 3, c0 = (q & 3) * 64;
            const char* bp = (const char*)((p == 1) ? g_xl : g_xh);
            long long sh = (long long)(tap - 1) * d * 512 + c0 * 2;
#pragma unroll
            for (int e = 0; e < 4; e++) {
                int t = t0 + arow[e] + (tap - 1) * d;
                int sz = (t >= 0 && t < T_N) ? 16 : 0;
                const char* src = sz ? (bp + abase[e] + sh) : bp;
                CP16(ad + adst[e], src, sz);
            }
        } else {
            int qb = (q - 36) * 64;
#pragma unroll
            for (int e = 0; e < 4; e++) {
                int s0 = qb + aseg[e] * 8;
                const char* src; int sz = 16;
                if (s0 < 80)       src = (const char*)g_ch + crow[e] + s0 * 2;
                else if (s0 < 160) src = (const char*)g_cl + crow[e] + (s0 - 80) * 2;
                else if (s0 < 240) src = (const char*)g_ch + crow[e] + (s0 - 160) * 2;
                else             { src = (const char*)g_ch; sz = 0; }
                CP16(ad + adst[e], src, sz);
            }
        }
    };
    auto stageB = [&](int q, int st) {
        const char* bsrc = (const char*)(g_wc + (size_t)(li * NQC + q) * 32768 + jt * 8192);
        uint32_t bd = sb + st * STG_B + 16384;
#pragma unroll
        for (int e = 0; e < 4; e++) {
            int idx = e * 256 + tid;
            CP16(bd + idx * 16, bsrc + idx * 16, 16);
        }
    };

    float c[2][8][4];
#pragma unroll
    for (int i = 0; i < 2; i++)
#pragma unroll
        for (int j = 0; j < 8; j++)
#pragma unroll
            for (int k = 0; k < 4; k++) c[i][j][k] = 0.f;

    int mb = (wid & 3) * 32, nb = (wid >> 2) * 64;
    int rA = lane & 15, cA = (lane >> 4) * 16;
    int rB = ((lane >> 4) & 1) * 8 + (lane & 7), cB = ((lane >> 3) & 1) * 16;

    stageA(0, 0); stageB(0, 0); CPCOMMIT();
    stageA(1, 1); stageB(1, 1); CPCOMMIT();

    for (int q = 0; q < NQC; q++) {
        int st = q % 3;
        if (q == NQC - 1) CPWAIT0(); else CPWAIT1();
        __syncthreads();
        if (q + 2 < NQC) {
            int st2 = (q + 2) % 3;
            stageA(q + 2, st2); stageB(q + 2, st2); CPCOMMIT();
        }
        uint32_t aB = sb + st * STG_B, bB = aB + 16384;
#pragma unroll
        for (int ks = 0; ks < 4; ks++) {
            uint32_t af[2][4], bf[4][4];
#pragma unroll
            for (int mi = 0; mi < 2; mi++)
                ldmx4(af[mi], aB + swz((uint32_t)(mb + mi * 16 + rA) * 128 + ks * 32 + cA));
#pragma unroll
            for (int nj = 0; nj < 4; nj++)
                ldmx4(bf[nj], bB + swz((uint32_t)(nb + nj * 16 + rB) * 128 + ks * 32 + cB));
#pragma unroll
            for (int mi = 0; mi < 2; mi++)
#pragma unroll
                for (int nj = 0; nj < 4; nj++) {
                    mma16816(c[mi][nj * 2],     af[mi], &bf[nj][0]);
                    mma16816(c[mi][nj * 2 + 1], af[mi], &bf[nj][2]);
                }
        }
    }
    __syncthreads();

    // epilogue: gate -> smem tiles (64 cols, pitch 72 bf16) -> coalesced global
    __nv_bfloat16* shh = (__nv_bfloat16*)sm;
    __nv_bfloat16* sll = (__nv_bfloat16*)(sm + 20480);
    const float* ib = ib_ + li * 512;
    const float* cb = cb_ + li * 512;
    int qrow = lane >> 2, qcol = lane & 3;
#pragma unroll
    for (int nt = 0; nt < 8; nt++) {
        int ol = (nb >> 1) + nt * 4 + qcol;      // 0..63
        int o = jt * 64 + ol;
        float b1 = ib[o] + cb[o];
        float b2 = ib[o + 256] + cb[o + 256];
#pragma unroll
        for (int mi = 0; mi < 2; mi++) {
            int tl = mb + mi * 16 + qrow;
            float a0 = tanhf(c[mi][nt][0] + b1) * sigf(c[mi][nt][1] + b2);
            float a1 = tanhf(c[mi][nt][2] + b1) * sigf(c[mi][nt][3] + b2);
            __nv_bfloat16 h0 = __float2bfloat16(a0);
            __nv_bfloat16 h1 = __float2bfloat16(a1);
            shh[tl * 72 + ol] = h0;
            sll[tl * 72 + ol] = __float2bfloat16(a0 - __bfloat162float(h0));
            shh[(tl + 8) * 72 + ol] = h1;
            sll[(tl + 8) * 72 + ol] = __float2bfloat16(a1 - __bfloat162float(h1));
        }
    }
    __syncthreads();
#pragma unroll
    for (int e = 0; e < 4; e++) {
        int idx = e * 256 + tid;
        int row = idx >> 3, sg = idx & 7;
        size_t go = (size_t)(b * T_N + t0 + row) * 256 + jt * 64;
        ((uint4*)(g_ah + go))[sg] = ((const uint4*)shh)[row * 9 + sg];
        ((uint4*)(g_al + go))[sg] = ((const uint4*)sll)[row * 9 + sg];
    }
}

// ---------------- rs GEMM + residual/skip ----------------
__global__ __launch_bounds__(256, 2) void rs_k(const float* __restrict__ rb_,
                                               int li, int last) {
    extern __shared__ char sm[];
    uint32_t sb = smem_u32(sm);
    int tid = threadIdx.x, wid = tid >> 5, lane = tid & 31;
    int t0 = blockIdx.x * 128, jt = blockIdx.y, b = blockIdx.z;

    uint32_t adst[4]; long long abase[4];
#pragma unroll
    for (int e = 0; e < 4; e++) {
        int idx = e * 256 + tid;
        int row = idx >> 3, seg = idx & 7;
        adst[e] = swz((uint32_t)row * 128 + seg * 16);
        abase[e] = (long long)((size_t)(b * T_N + t0 + row) * 256) * 2 + seg * 16;
    }

    auto stageA = [&](int q, int st) {
        int p = q >> 2, c0 = (q & 3) * 64;
        const char* bp = (const char*)((p == 1) ? g_al : g_ah);
        uint32_t ad = sb + st * STG_B;
#pragma unroll
        for (int e = 0; e < 4; e++)
            CP16(ad + adst[e], bp + abase[e] + c0 * 2, 16);
    };
    auto stageB = [&](int q, int st) {
        const char* bsrc = (const char*)(g_wr + (size_t)(li * 12 + q) * 32768 + jt * 8192);
        uint32_t bd = sb + st * STG_B + 16384;
#pragma unroll
        for (int e = 0; e < 4; e++) {
            int idx = e * 256 + tid;
            CP16(bd + idx * 16, bsrc + idx * 16, 16);
        }
    };

    float c[2][8][4];
#pragma unroll
    for (int i = 0; i < 2; i++)
#pragma unroll
        for (int j = 0; j < 8; j++)
#pragma unroll
            for (int k = 0; k < 4; k++) c[i][j][k] = 0.f;

    int mb = (wid & 3) * 32, nb = (wid >> 2) * 64;
    int rA = lane & 15, cA = (lane >> 4) * 16;
    int rB = ((lane >> 4) & 1) * 8 + (lane & 7), cB = ((lane >> 3) & 1) * 16;

    stageA(0, 0); stageB(0, 0); CPCOMMIT();
    stageA(1, 1); stageB(1, 1); CPCOMMIT();

    for (int q = 0; q < 12; q++) {
        int st = q % 3;
        if (q == 11) CPWAIT0(); else CPWAIT1();
        __syncthreads();
        if (q + 2 < 12) {
            int st2 = (q + 2) % 3;
            stageA(q + 2, st2); stageB(q + 2, st2); CPCOMMIT();
        }
        uint32_t aB = sb + st * STG_B, bB = aB + 16384;
#pragma unroll
        for (int ks = 0; ks < 4; ks++) {
            uint32_t af[2][4], bf[4][4];
#pragma unroll
            for (int mi = 0; mi < 2; mi++)
                ldmx4(af[mi], aB + swz((uint32_t)(mb + mi * 16 + rA) * 128 + ks * 32 + cA));
#pragma unroll
            for (int nj = 0; nj < 4; nj++)
                ldmx4(bf[nj], bB + swz((uint32_t)(nb + nj * 16 + rB) * 128 + ks * 32 + cB));
#pragma unroll
            for (int mi = 0; mi < 2; mi++)
#pragma unroll
                for (int nj = 0; nj < 4; nj++) {
                    mma16816(c[mi][nj * 2],     af[mi], &bf[nj][0]);
                    mma16816(c[mi][nj * 2 + 1], af[mi], &bf[nj][2]);
                }
        }
    }
    __syncthreads();

    // epilogue via smem tiles (fp32, 64 cols, pitch 68)
    float* sr = (float*)sm;
    float* ss = (float*)(sm + 34816);
    int qrow = lane >> 2, qcol = lane & 3;
#pragma unroll
    for (int nt = 0; nt < 8; nt++) {
        int ol = (nb >> 1) + nt * 4 + qcol;
#pragma unroll
        for (int mi = 0; mi < 2; mi++) {
            int tl = mb + mi * 16 + qrow;
            sr[tl * 68 + ol] = c[mi][nt][0];
            ss[tl * 68 + ol] = c[mi][nt][1];
            sr[(tl + 8) * 68 + ol] = c[mi][nt][2];
            ss[(tl + 8) * 68 + ol] = c[mi][nt][3];
        }
    }
    __syncthreads();
    const float* rb = rb_ + li * 512;
#pragma unroll
    for (int e = 0; e < 8; e++) {
        int idx = e * 256 + tid;
        int row = idx >> 4, sg = idx & 15;
        int o = jt * 64 + sg * 4;
        size_t go = (size_t)(b * T_N + t0 + row) * 256 + o;
        float4 rv = ((const float4*)sr)[row * 17 + sg];
        float4 b1 = *(const float4*)(rb + o);
        if (!last) {
            float4 xv = *(const float4*)(g_x + go);
            float4 v = make_float4(xv.x + rv.x + b1.x, xv.y + rv.y + b1.y,
                                   xv.z + rv.z + b1.z, xv.w + rv.w + b1.w);
            *(float4*)(g_x + go) = v;
            __nv_bfloat16 h0 = __float2bfloat16(v.x), h1 = __float2bfloat16(v.y);
            __nv_bfloat16 h2 = __float2bfloat16(v.z), h3 = __float2bfloat16(v.w);
            __nv_bfloat162 hh0 = {h0, h1}, hh1 = {h2, h3};
            *(__nv_bfloat162*)(g_xh + go) = hh0;
            *(__nv_bfloat162*)(g_xh + go + 2) = hh1;
            __nv_bfloat162 ll0 = {__float2bfloat16(v.x - __bfloat162float(h0)),
                                  __float2bfloat16(v.y - __bfloat162float(h1))};
            __nv_bfloat162 ll1 = {__float2bfloat16(v.z - __bfloat162float(h2)),
                                  __float2bfloat16(v.w - __bfloat162float(h3))};
            *(__nv_bfloat162*)(g_xl + go) = ll0;
            *(__nv_bfloat162*)(g_xl + go + 2) = ll1;
            float4 sv = ((const float4*)ss)[row * 17 + sg];
            float4 b2 = *(const float4*)(rb + 256 + o);
            float4 ov = *(const float4*)(g_oa + go);
            ov.x += sv.x + b2.x; ov.y += sv.y + b2.y;
            ov.z += sv.z + b2.z; ov.w += sv.w + b2.w;
            *(float4*)(g_oa + go) = ov;
        } else {
            float4 ov = *(const float4*)(g_oa + go);
            ov.x += rv.x + b1.x; ov.y += rv.y + b1.y;
            ov.z += rv.z + b1.z; ov.w += rv.w + b1.w;
            *(float4*)(g_oa + go) = ov;
        }
    }
}

// ---------------- end conv + affine ----------------
__global__ void end_k(const float* __restrict__ f, const float* __restrict__ ew,
                      const float* __restrict__ eb, float* __restrict__ out) {
    __shared__ float w[2048];
    int tid = threadIdx.x;
    for (int e = tid; e < 2048; e += 256) w[e] = ew[e];
    __syncthreads();
    int idx = blockIdx.x * 256 + tid;
    int t = idx & (T_N - 1), b = idx >> 12;
    float acc[8];
#pragma unroll
    for (int o = 0; o < 8; o++) acc[o] = eb[o];
    const float4* oa = (const float4*)(g_oa + (size_t)(b * T_N + t) * 256);
    for (int c4 = 0; c4 < 64; c4++) {
        float4 v = oa[c4];
#pragma unroll
        for (int o = 0; o < 8; o++) {
            acc[o] = fmaf(v.x, w[o * 256 + c4 * 4],     acc[o]);
            acc[o] = fmaf(v.y, w[o * 256 + c4 * 4 + 1], acc[o]);
            acc[o] = fmaf(v.z, w[o * 256 + c4 * 4 + 2], acc[o]);
            acc[o] = fmaf(v.w, w[o * 256 + c4 * 4 + 3], acc[o]);
        }
    }
    const float* fb = f + (size_t)b * 8 * T_N + t;
    float* cc = out + (size_t)b * 8 * T_N + t;
    float* lo = out + (size_t)B_N * 8 * T_N + (size_t)b * 4 * T_N + t;
#pragma unroll
    for (int l = 0; l < 4; l++) {
        cc[(size_t)l * T_N] = fb[(size_t)l * T_N];
        float ls = acc[4 + l];
        cc[(size_t)(4 + l) * T_N] = expf(ls) * fb[(size_t)(4 + l) * T_N] + acc[l];
        lo[(size_t)l * T_N] = ls;
    }
}

// ---------------- launch ----------------
static const int DIL[NL] = {1, 2, 4, 8, 16, 32, 64, 128};

extern "C" void kernel_launch(void* const* d_in, const int* in_sizes, int n_in,
                              void* d_out, int out_size) {
    const float* forecast = (const float*)d_in[0];
    const float* context  = (const float*)d_in[1];
    const float* start_w  = (const float*)d_in[2];
    const float* start_b  = (const float*)d_in[3];
    const float* cond_w   = (const float*)d_in[4];
    const float* cond_b   = (const float*)d_in[5];
    const float* in_w     = (const float*)d_in[6];
    const float* in_b     = (const float*)d_in[7];
    const float* rs_w     = (const float*)d_in[8];
    const float* rs_b     = (const float*)d_in[9];
    const float* end_w    = (const float*)d_in[10];
    const float* end_b    = (const float*)d_in[11];
    float* out = (float*)d_out;
    (void)in_sizes; (void)n_in; (void)out_size;

    cudaFuncSetAttribute(conv_k, cudaFuncAttributeMaxDynamicSharedMemorySize, GEMM_SMEM);
    cudaFuncSetAttribute(rs_k,   cudaFuncAttributeMaxDynamicSharedMemorySize, GEMM_SMEM);

    prep_all<<<(NL * (NQC + 12) * 32768 + 255) / 256, 256>>>(in_w, cond_w, rs_w);
    ctx_prep<<<dim3(T_N / 32, B_N), 256>>>(context);
    start_k<<<dim3(T_N / 128, B_N), 256>>>(forecast, start_w, start_b);

    dim3 grid(T_N / 128, 4, B_N);
    for (int li = 0; li < NL; li++) {
        conv_k<<<grid, 256, GEMM_SMEM>>>(in_b, cond_b, li, DIL[li]);
        rs_k<<<grid, 256, GEMM_SMEM>>>(rs_b, li, li == NL - 1 ? 1 : 0);
    }
    end_k<<<(B_N * T_N) / 256, 256>>>(forecast, end_w, end_b, out);
}

// round 11
// speedup vs baseline: 2.6485x; 1.0089x over previous
#include <cuda_runtime.h>
#include <cuda_bf16.h>
#include <cstdint>

#define T_N 4096
#define B_N 8
#define NL  8
#define NQC 40               // conv chunks: 36 x-parts + 4 packed ctx (240 slots)
#define STG_B 32768          // per stage: 16KB A + 16KB B
#define GEMM_SMEM 98304      // 3 stages

// ---------------- device scratch ----------------
__device__ __align__(16) float         g_x [B_N*T_N*256];
__device__ __align__(16) __nv_bfloat16 g_xh[B_N*T_N*256];
__device__ __align__(16) __nv_bfloat16 g_xl[B_N*T_N*256];
__device__ __align__(16) __nv_bfloat16 g_ah[B_N*T_N*256];
__device__ __align__(16) __nv_bfloat16 g_al[B_N*T_N*256];
__device__ __align__(16) float         g_oa[B_N*T_N*256];
__device__ __align__(16) __nv_bfloat16 g_ch[B_N*T_N*80];
__device__ __align__(16) __nv_bfloat16 g_cl[B_N*T_N*80];
__device__ __align__(16) __nv_bfloat16 g_wc[(size_t)NL*NQC*32768];
__device__ __align__(16) __nv_bfloat16 g_wr[(size_t)NL*12*32768];

// ---------------- helpers ----------------
__device__ __forceinline__ uint32_t smem_u32(const void* p) {
    uint32_t a;
    asm("{ .reg .u64 t; cvta.to.shared.u64 t, %1; cvt.u32.u64 %0, t; }" : "=r"(a) : "l"(p));
    return a;
}
__device__ __forceinline__ uint32_t swz(uint32_t x) { return x ^ ((x >> 3) & 0x70); }

#define CP16(dst, src, sz) \
    asm volatile("cp.async.cg.shared.global [%0], [%1], 16, %2;" \
        :: "r"(dst), "l"(src), "r"(sz) : "memory")
#define CPCOMMIT() asm volatile("cp.async.commit_group;" ::: "memory")
#define CPWAIT1()  asm volatile("cp.async.wait_group 1;" ::: "memory")
#define CPWAIT0()  asm volatile("cp.async.wait_group 0;" ::: "memory")

__device__ __forceinline__ void ldmx4(uint32_t* r, uint32_t a) {
    asm volatile("ldmatrix.sync.aligned.m8n8.x4.shared.b16 {%0,%1,%2,%3}, [%4];"
        : "=r"(r[0]), "=r"(r[1]), "=r"(r[2]), "=r"(r[3]) : "r"(a));
}
__device__ __forceinline__ void mma16816(float* c, const uint32_t* a, const uint32_t* b) {
    asm volatile("mma.sync.aligned.m16n8k16.row.col.f32.bf16.bf16.f32 "
        "{%0,%1,%2,%3}, {%4,%5,%6,%7}, {%8,%9}, {%0,%1,%2,%3};"
        : "+f"(c[0]), "+f"(c[1]), "+f"(c[2]), "+f"(c[3])
        : "r"(a[0]), "r"(a[1]), "r"(a[2]), "r"(a[3]), "r"(b[0]), "r"(b[1]));
}
__device__ __forceinline__ float sigf(float x) { return 1.f / (1.f + __expf(-x)); }

// ---------------- merged weight-image prep (16KB quarter tiles) ----------------
__global__ void prep_all(const float* __restrict__ in_w,
                         const float* __restrict__ cond_w,
                         const float* __restrict__ rs_w) {
    int idx = blockIdx.x * 256 + threadIdx.x;
    const int NC = NL * NQC * 32768;
    if (idx < NC) {
        int li = idx / (NQC * 32768);
        int r  = idx % (NQC * 32768);
        int q = r >> 15, rr = r & 32767;
        int ng = rr >> 6, k = rr & 63;
        int jt = ng >> 7, nq = ng & 127;
        int o = jt * 64 + (nq >> 1), s = nq & 1;
        int och = o + s * 256;
        float w; int p;
        if (q < 36) {
            int pp = q >> 2; p = pp % 3;
            int tap = pp / 3, c = (q & 3) * 64 + k;
            w = in_w[((size_t)(li * 512 + och) * 256 + c) * 3 + tap];
        } else {
            int sidx = (q - 36) * 64 + k;
            if (sidx < 80)       { w = cond_w[(size_t)(li * 512 + och) * 80 + sidx];        p = 0; }
            else if (sidx < 160) { w = cond_w[(size_t)(li * 512 + och) * 80 + sidx - 80];   p = 0; }
            else if (sidx < 240) { w = cond_w[(size_t)(li * 512 + och) * 80 + sidx - 160];  p = 2; }
            else                 { w = 0.f; p = 0; }
        }
        __nv_bfloat16 h = __float2bfloat16(w);
        if (p == 2) h = __float2bfloat16(w - __bfloat162float(h));
        g_wc[(size_t)(li * NQC + q) * 32768 + jt * 8192 + (swz((uint32_t)nq * 128 + k * 2) >> 1)] = h;
    } else {
        idx -= NC;
        if (idx >= NL * 12 * 32768) return;
        int li = idx / (12 * 32768);
        int r  = idx % (12 * 32768);
        int q = r >> 15, rr = r & 32767;
        int ng = rr >> 6, k = rr & 63;
        int jt = ng >> 7, nq = ng & 127;
        int o = jt * 64 + (nq >> 1), s = nq & 1;
        int och = o + s * 256;
        int p = q >> 2, c = (q & 3) * 64 + k;
        float w = rs_w[(size_t)(li * 512 + och) * 256 + c];
        __nv_bfloat16 h = __float2bfloat16(w);
        if (p == 2) h = __float2bfloat16(w - __bfloat162float(h));
        g_wr[(size_t)(li * 12 + q) * 32768 + jt * 8192 + (swz((uint32_t)nq * 128 + k * 2) >> 1)] = h;
    }
}

// ---------------- context transpose+split ----------------
__global__ void ctx_prep(const float* __restrict__ ctx) {
    __shared__ float tile[80][33];
    int b = blockIdx.y, t0 = blockIdx.x * 32, tid = threadIdx.x;
    int i = tid & 31, m0 = tid >> 5;
    for (int mm = m0; mm < 80; mm += 8)
        tile[mm][i] = ctx[((size_t)b * 80 + mm) * T_N + t0 + i];
    __syncthreads();
    int tt = tid >> 3, sg = tid & 7;
    size_t rb = ((size_t)b * T_N + t0 + tt) * 80;
    for (int e = 0; e < 10; e++) {
        int m = sg * 10 + e;
        float v = tile[m][tt];
        __nv_bfloat16 h = __float2bfloat16(v);
        g_ch[rb + m] = h;
        g_cl[rb + m] = __float2bfloat16(v - __bfloat162float(h));
    }
}

// ---------------- start conv ----------------
__global__ void start_k(const float* __restrict__ f, const float* __restrict__ sw,
                        const float* __restrict__ sb) {
    __shared__ float ft[4][128];
    int t0 = blockIdx.x * 128, b = blockIdx.y, c = threadIdx.x;
    for (int e = 0; e < 2; e++) {
        int idx = e * 256 + c;
        ft[idx >> 7][idx & 127] = f[((size_t)b * 8 + (idx >> 7)) * T_N + t0 + (idx & 127)];
    }
    float w0 = sw[c * 4], w1 = sw[c * 4 + 1], w2 = sw[c * 4 + 2], w3 = sw[c * 4 + 3];
    float bb = sb[c];
    __syncthreads();
    for (int t = 0; t < 128; t++) {
        float v = fmaf(ft[3][t], w3, fmaf(ft[2][t], w2, fmaf(ft[1][t], w1, fmaf(ft[0][t], w0, bb))));
        size_t o = ((size_t)b * T_N + t0 + t) * 256 + c;
        g_x[o] = v; g_oa[o] = 0.f;
        __nv_bfloat16 h = __float2bfloat16(v);
        g_xh[o] = h;
        g_xl[o] = __float2bfloat16(v - __bfloat162float(h));
    }
}

// ---------------- conv GEMM + gate (128t x 128n per CTA, 2 CTAs/SM) ----------------
__global__ __launch_bounds__(256, 2) void conv_k(const float* __restrict__ ib_,
                                                 const float* __restrict__ cb_,
                                                 int li, int d) {
    extern __shared__ char sm[];
    uint32_t sb = smem_u32(sm);
    int tid = threadIdx.x, wid = tid >> 5, lane = tid & 31;
    int t0 = blockIdx.x * 128, jt = blockIdx.y, b = blockIdx.z;

    // collapsed staging constants: e-th element is an arithmetic progression
    int row0 = tid >> 3, seg = tid & 7;
    uint32_t adst0  = (uint32_t)row0 * 128 + (((uint32_t)seg * 16) ^ (((uint32_t)row0 & 7) << 4));
    uint32_t abase0 = ((uint32_t)(b * T_N + t0 + row0)) * 512 + (uint32_t)seg * 16;
    uint32_t crow0  = ((uint32_t)(b * T_N + t0 + row0)) * 160;

    auto stageA = [&](int q, int st) {
        uint32_t ad = sb + st * STG_B + adst0;
        if (q < 36) {
            int pp = q >> 2, p = pp % 3, tap = pp / 3, c0 = (q & 3) * 64;
            const char* bp = (const char*)((p == 1) ? g_xl : g_xh);
            int tsh = (tap - 1) * d;
            const char* base = bp + abase0 + (long long)tsh * 512 + c0 * 2;
#pragma unroll
            for (int e = 0; e < 4; e++) {
                int t = t0 + row0 + 32 * e + tsh;
                int sz = (t >= 0 && t < T_N) ? 16 : 0;
                const char* src = sz ? (base + e * 16384) : bp;
                CP16(ad + e * 4096, src, sz);
            }
        } else {
            int s0 = (q - 36) * 64 + seg * 8;
            const char* base; int sz = 16;
            if (s0 < 80)       base = (const char*)g_ch + crow0 + s0 * 2;
            else if (s0 < 160) base = (const char*)g_cl + crow0 + (s0 - 80) * 2;
            else if (s0 < 240) base = (const char*)g_ch + crow0 + (s0 - 160) * 2;
            else             { base = (const char*)g_ch; sz = 0; }
#pragma unroll
            for (int e = 0; e < 4; e++)
                CP16(ad + e * 4096, base + (sz ? e * 5120 : 0), sz);
        }
    };
    auto stageB = [&](int q, int st) {
        const char* bsrc = (const char*)(g_wc + (size_t)(li * NQC + q) * 32768 + jt * 8192) + tid * 16;
        uint32_t bd = sb + st * STG_B + 16384 + tid * 16;
#pragma unroll
        for (int e = 0; e < 4; e++)
            CP16(bd + e * 4096, bsrc + e * 4096, 16);
    };

    float c[2][8][4];
#pragma unroll
    for (int i = 0; i < 2; i++)
#pragma unroll
        for (int j = 0; j < 8; j++)
#pragma unroll
            for (int k = 0; k < 4; k++) c[i][j][k] = 0.f;

    int mb = (wid & 3) * 32, nb = (wid >> 2) * 64;
    int rA = lane & 15, cA = (lane >> 4) * 16;
    int rB = ((lane >> 4) & 1) * 8 + (lane & 7), cB = ((lane >> 3) & 1) * 16;

    // swizzle hoist: swz(row*128 + koff) = row*128 + (koff ^ ((row&7)<<4))
    uint32_t aRow = (uint32_t)(mb + rA) * 128;     // +2048 per mi
    uint32_t bRow = (uint32_t)(nb + rB) * 128;     // +2048 per nj
    uint32_t axr = ((uint32_t)rA & 7) << 4;
    uint32_t bxr = ((uint32_t)rB & 7) << 4;
    uint32_t kxA[4], kxB[4];
#pragma unroll
    for (int ks = 0; ks < 4; ks++) {
        kxA[ks] = ((uint32_t)(ks * 32 + cA)) ^ axr;
        kxB[ks] = ((uint32_t)(ks * 32 + cB)) ^ bxr;
    }

    stageA(0, 0); stageB(0, 0); CPCOMMIT();
    stageA(1, 1); stageB(1, 1); CPCOMMIT();

    for (int q = 0; q < NQC; q++) {
        int st = q % 3;
        if (q == NQC - 1) CPWAIT0(); else CPWAIT1();
        __syncthreads();
        if (q + 2 < NQC) {
            int st2 = (q + 2) % 3;
            stageA(q + 2, st2); stageB(q + 2, st2); CPCOMMIT();
        }
        uint32_t aB = sb + st * STG_B, bB = aB + 16384;
        uint32_t aA0 = aB + aRow, aA1 = aA0 + 2048;
        uint32_t bBr = bB + bRow;

        uint32_t af[2][2][4], bf[2][4];
        ldmx4(af[0][0], aA0 + kxA[0]);
        ldmx4(af[0][1], aA1 + kxA[0]);
        ldmx4(bf[0], bBr + kxB[0]);
#pragma unroll
        for (int ks = 0; ks < 4; ks++) {
            int cs = ks & 1, ns = cs ^ 1;
            if (ks < 3) {
                ldmx4(af[ns][0], aA0 + kxA[ks + 1]);
                ldmx4(af[ns][1], aA1 + kxA[ks + 1]);
            }
#pragma unroll
            for (int nj = 0; nj < 4; nj++) {
                int cb2 = nj & 1, nb2 = cb2 ^ 1;
                if (nj < 3)      ldmx4(bf[nb2], bBr + (nj + 1) * 2048 + kxB[ks]);
                else if (ks < 3) ldmx4(bf[nb2], bBr + kxB[ks + 1]);
                mma16816(c[0][nj * 2],     af[cs][0], &bf[cb2][0]);
                mma16816(c[0][nj * 2 + 1], af[cs][0], &bf[cb2][2]);
                mma16816(c[1][nj * 2],     af[cs][1], &bf[cb2][0]);
                mma16816(c[1][nj * 2 + 1], af[cs][1], &bf[cb2][2]);
            }
        }
    }
    __syncthreads();

    // epilogue: gate -> smem tiles (64 cols, pitch 72 bf16) -> coalesced global
    __nv_bfloat16* shh = (__nv_bfloat16*)sm;
    __nv_bfloat16* sll = (__nv_bfloat16*)(sm + 20480);
    const float* ib = ib_ + li * 512;
    const float* cb = cb_ + li * 512;
    int qrow = lane >> 2, qcol = lane & 3;
#pragma unroll
    for (int nt = 0; nt < 8; nt++) {
        int ol = (nb >> 1) + nt * 4 + qcol;      // 0..63
        int o = jt * 64 + ol;
        float b1 = ib[o] + cb[o];
        float b2 = ib[o + 256] + cb[o + 256];
#pragma unroll
        for (int mi = 0; mi < 2; mi++) {
            int tl = mb + mi * 16 + qrow;
            float a0 = tanhf(c[mi][nt][0] + b1) * sigf(c[mi][nt][1] + b2);
            float a1 = tanhf(c[mi][nt][2] + b1) * sigf(c[mi][nt][3] + b2);
            __nv_bfloat16 h0 = __float2bfloat16(a0);
            __nv_bfloat16 h1 = __float2bfloat16(a1);
            shh[tl * 72 + ol] = h0;
            sll[tl * 72 + ol] = __float2bfloat16(a0 - __bfloat162float(h0));
            shh[(tl + 8) * 72 + ol] = h1;
            sll[(tl + 8) * 72 + ol] = __float2bfloat16(a1 - __bfloat162float(h1));
        }
    }
    __syncthreads();
#pragma unroll
    for (int e = 0; e < 4; e++) {
        int idx = e * 256 + tid;
        int row = idx >> 3, sg = idx & 7;
        size_t go = (size_t)(b * T_N + t0 + row) * 256 + jt * 64;
        ((uint4*)(g_ah + go))[sg] = ((const uint4*)shh)[row * 9 + sg];
        ((uint4*)(g_al + go))[sg] = ((const uint4*)sll)[row * 9 + sg];
    }
}

// ---------------- rs GEMM + residual/skip ----------------
__global__ __launch_bounds__(256, 2) void rs_k(const float* __restrict__ rb_,
                                               int li, int last) {
    extern __shared__ char sm[];
    uint32_t sb = smem_u32(sm);
    int tid = threadIdx.x, wid = tid >> 5, lane = tid & 31;
    int t0 = blockIdx.x * 128, jt = blockIdx.y, b = blockIdx.z;

    int row0 = tid >> 3, seg = tid & 7;
    uint32_t adst0  = (uint32_t)row0 * 128 + (((uint32_t)seg * 16) ^ (((uint32_t)row0 & 7) << 4));
    uint32_t abase0 = ((uint32_t)(b * T_N + t0 + row0)) * 512 + (uint32_t)seg * 16;

    auto stageA = [&](int q, int st) {
        int p = q >> 2, c0 = (q & 3) * 64;
        const char* base = (const char*)((p == 1) ? g_al : g_ah) + abase0 + c0 * 2;
        uint32_t ad = sb + st * STG_B + adst0;
#pragma unroll
        for (int e = 0; e < 4; e++)
            CP16(ad + e * 4096, base + e * 16384, 16);
    };
    auto stageB = [&](int q, int st) {
        const char* bsrc = (const char*)(g_wr + (size_t)(li * 12 + q) * 32768 + jt * 8192) + tid * 16;
        uint32_t bd = sb + st * STG_B + 16384 + tid * 16;
#pragma unroll
        for (int e = 0; e < 4; e++)
            CP16(bd + e * 4096, bsrc + e * 4096, 16);
    };

    float c[2][8][4];
#pragma unroll
    for (int i = 0; i < 2; i++)
#pragma unroll
        for (int j = 0; j < 8; j++)
#pragma unroll
            for (int k = 0; k < 4; k++) c[i][j][k] = 0.f;

    int mb = (wid & 3) * 32, nb = (wid >> 2) * 64;
    int rA = lane & 15, cA = (lane >> 4) * 16;
    int rB = ((lane >> 4) & 1) * 8 + (lane & 7), cB = ((lane >> 3) & 1) * 16;

    uint32_t aRow = (uint32_t)(mb + rA) * 128;
    uint32_t bRow = (uint32_t)(nb + rB) * 128;
    uint32_t axr = ((uint32_t)rA & 7) << 4;
    uint32_t bxr = ((uint32_t)rB & 7) << 4;
    uint32_t kxA[4], kxB[4];
#pragma unroll
    for (int ks = 0; ks < 4; ks++) {
        kxA[ks] = ((uint32_t)(ks * 32 + cA)) ^ axr;
        kxB[ks] = ((uint32_t)(ks * 32 + cB)) ^ bxr;
    }

    stageA(0, 0); stageB(0, 0); CPCOMMIT();
    stageA(1, 1); stageB(1, 1); CPCOMMIT();

    for (int q = 0; q < 12; q++) {
        int st = q % 3;
        if (q == 11) CPWAIT0(); else CPWAIT1();
        __syncthreads();
        if (q + 2 < 12) {
            int st2 = (q + 2) % 3;
            stageA(q + 2, st2); stageB(q + 2, st2); CPCOMMIT();
        }
        uint32_t aB = sb + st * STG_B, bB = aB + 16384;
        uint32_t aA0 = aB + aRow, aA1 = aA0 + 2048;
        uint32_t bBr = bB + bRow;

        uint32_t af[2][2][4], bf[2][4];
        ldmx4(af[0][0], aA0 + kxA[0]);
        ldmx4(af[0][1], aA1 + kxA[0]);
        ldmx4(bf[0], bBr + kxB[0]);
#pragma unroll
        for (int ks = 0; ks < 4; ks++) {
            int cs = ks & 1, ns = cs ^ 1;
            if (ks < 3) {
                ldmx4(af[ns][0], aA0 + kxA[ks + 1]);
                ldmx4(af[ns][1], aA1 + kxA[ks + 1]);
            }
#pragma unroll
            for (int nj = 0; nj < 4; nj++) {
                int cb2 = nj & 1, nb2 = cb2 ^ 1;
                if (nj < 3)      ldmx4(bf[nb2], bBr + (nj + 1) * 2048 + kxB[ks]);
                else if (ks < 3) ldmx4(bf[nb2], bBr + kxB[ks + 1]);
                mma16816(c[0][nj * 2],     af[cs][0], &bf[cb2][0]);
                mma16816(c[0][nj * 2 + 1], af[cs][0], &bf[cb2][2]);
                mma16816(c[1][nj * 2],     af[cs][1], &bf[cb2][0]);
                mma16816(c[1][nj * 2 + 1], af[cs][1], &bf[cb2][2]);
            }
        }
    }
    __syncthreads();

    // epilogue via smem tiles (fp32, 64 cols, pitch 68)
    float* sr = (float*)sm;
    float* ss = (float*)(sm + 34816);
    int qrow = lane >> 2, qcol = lane & 3;
#pragma unroll
    for (int nt = 0; nt < 8; nt++) {
        int ol = (nb >> 1) + nt * 4 + qcol;
#pragma unroll
        for (int mi = 0; mi < 2; mi++) {
            int tl = mb + mi * 16 + qrow;
            sr[tl * 68 + ol] = c[mi][nt][0];
            ss[tl * 68 + ol] = c[mi][nt][1];
            sr[(tl + 8) * 68 + ol] = c[mi][nt][2];
            ss[(tl + 8) * 68 + ol] = c[mi][nt][3];
        }
    }
    __syncthreads();
    const float* rb = rb_ + li * 512;
#pragma unroll
    for (int e = 0; e < 8; e++) {
        int idx = e * 256 + tid;
        int row = idx >> 4, sg = idx & 15;
        int o = jt * 64 + sg * 4;
        size_t go = (size_t)(b * T_N + t0 + row) * 256 + o;
        float4 rv = ((const float4*)sr)[row * 17 + sg];
        float4 b1 = *(const float4*)(rb + o);
        if (!last) {
            float4 xv = *(const float4*)(g_x + go);
            float4 v = make_float4(xv.x + rv.x + b1.x, xv.y + rv.y + b1.y,
                                   xv.z + rv.z + b1.z, xv.w + rv.w + b1.w);
            *(float4*)(g_x + go) = v;
            __nv_bfloat16 h0 = __float2bfloat16(v.x), h1 = __float2bfloat16(v.y);
            __nv_bfloat16 h2 = __float2bfloat16(v.z), h3 = __float2bfloat16(v.w);
            __nv_bfloat162 hh0 = {h0, h1}, hh1 = {h2, h3};
            *(__nv_bfloat162*)(g_xh + go) = hh0;
            *(__nv_bfloat162*)(g_xh + go + 2) = hh1;
            __nv_bfloat162 ll0 = {__float2bfloat16(v.x - __bfloat162float(h0)),
                                  __float2bfloat16(v.y - __bfloat162float(h1))};
            __nv_bfloat162 ll1 = {__float2bfloat16(v.z - __bfloat162float(h2)),
                                  __float2bfloat16(v.w - __bfloat162float(h3))};
            *(__nv_bfloat162*)(g_xl + go) = ll0;
            *(__nv_bfloat162*)(g_xl + go + 2) = ll1;
            float4 sv = ((const float4*)ss)[row * 17 + sg];
            float4 b2 = *(const float4*)(rb + 256 + o);
            float4 ov = *(const float4*)(g_oa + go);
            ov.x += sv.x + b2.x; ov.y += sv.y + b2.y;
            ov.z += sv.z + b2.z; ov.w += sv.w + b2.w;
            *(float4*)(g_oa + go) = ov;
        } else {
            float4 ov = *(const float4*)(g_oa + go);
            ov.x += rv.x + b1.x; ov.y += rv.y + b1.y;
            ov.z += rv.z + b1.z; ov.w += rv.w + b1.w;
            *(float4*)(g_oa + go) = ov;
        }
    }
}

// ---------------- end conv + affine ----------------
__global__ void end_k(const float* __restrict__ f, const float* __restrict__ ew,
                      const float* __restrict__ eb, float* __restrict__ out) {
    __shared__ float w[2048];
    int tid = threadIdx.x;
    for (int e = tid; e < 2048; e += 256) w[e] = ew[e];
    __syncthreads();
    int idx = blockIdx.x * 256 + tid;
    int t = idx & (T_N - 1), b = idx >> 12;
    float acc[8];
#pragma unroll
    for (int o = 0; o < 8; o++) acc[o] = eb[o];
    const float4* oa = (const float4*)(g_oa + (size_t)(b * T_N + t) * 256);
    for (int c4 = 0; c4 < 64; c4++) {
        float4 v = oa[c4];
#pragma unroll
        for (int o = 0; o < 8; o++) {
            acc[o] = fmaf(v.x, w[o * 256 + c4 * 4],     acc[o]);
            acc[o] = fmaf(v.y, w[o * 256 + c4 * 4 + 1], acc[o]);
            acc[o] = fmaf(v.z, w[o * 256 + c4 * 4 + 2], acc[o]);
            acc[o] = fmaf(v.w, w[o * 256 + c4 * 4 + 3], acc[o]);
        }
    }
    const float* fb = f + (size_t)b * 8 * T_N + t;
    float* cc = out + (size_t)b * 8 * T_N + t;
    float* lo = out + (size_t)B_N * 8 * T_N + (size_t)b * 4 * T_N + t;
#pragma unroll
    for (int l = 0; l < 4; l++) {
        cc[(size_t)l * T_N] = fb[(size_t)l * T_N];
        float ls = acc[4 + l];
        cc[(size_t)(4 + l) * T_N] = expf(ls) * fb[(size_t)(4 + l) * T_N] + acc[l];
        lo[(size_t)l * T_N] = ls;
    }
}

// ---------------- launch ----------------
static const int DIL[NL] = {1, 2, 4, 8, 16, 32, 64, 128};

extern "C" void kernel_launch(void* const* d_in, const int* in_sizes, int n_in,
                              void* d_out, int out_size) {
    const float* forecast = (const float*)d_in[0];
    const float* context  = (const float*)d_in[1];
    const float* start_w  = (const float*)d_in[2];
    const float* start_b  = (const float*)d_in[3];
    const float* cond_w   = (const float*)d_in[4];
    const float* cond_b   = (const float*)d_in[5];
    const float* in_w     = (const float*)d_in[6];
    const float* in_b     = (const float*)d_in[7];
    const float* rs_w     = (const float*)d_in[8];
    const float* rs_b     = (const float*)d_in[9];
    const float* end_w    = (const float*)d_in[10];
    const float* end_b    = (const float*)d_in[11];
    float* out = (float*)d_out;
    (void)in_sizes; (void)n_in; (void)out_size;

    cudaFuncSetAttribute(conv_k, cudaFuncAttributeMaxDynamicSharedMemorySize, GEMM_SMEM);
    cudaFuncSetAttribute(rs_k,   cudaFuncAttributeMaxDynamicSharedMemorySize, GEMM_SMEM);

    prep_all<<<(NL * (NQC + 12) * 32768 + 255) / 256, 256>>>(in_w, cond_w, rs_w);
    ctx_prep<<<dim3(T_N / 32, B_N), 256>>>(context);
    start_k<<<dim3(T_N / 128, B_N), 256>>>(forecast, start_w, start_b);

    dim3 grid(T_N / 128, 4, B_N);
    for (int li = 0; li < NL; li++) {
        conv_k<<<grid, 256, GEMM_SMEM>>>(in_b, cond_b, li, DIL[li]);
        rs_k<<<grid, 256, GEMM_SMEM>>>(rs_b, li, li == NL - 1 ? 1 : 0);
    }
    end_k<<<(B_N * T_N) / 256, 256>>>(forecast, end_w, end_b, out);
}